// round 1
// baseline (speedup 1.0000x reference)
#include <cuda_runtime.h>
#include <math.h>

// ---------------------------------------------------------------------------
// GAT 4-layer network. Strategy:
//   - Build CSR (edges sorted by dst) once per call: histogram + scan + scatter
//   - Per layer: SGEMM (h = x@W), attention coefficients, per-node segment
//     softmax (no atomics, warp per (node,head)), per-node aggregation
//     (block per node, register accumulators, coalesced row gathers),
//     BatchNorm + ELU (layers 1-3), log_softmax (layer 4).
// All scratch in __device__ globals (no allocation).
// ---------------------------------------------------------------------------

#define MAXN 20000
#define MAXE 360000   // E + N self loops = 340000; margin
#define MAXF 512
#define MAXH 8
#define SCAN_B 512

__device__ float g_h[MAXN * MAXF];     // GEMM output (pre-aggregation features)
__device__ float g_y[MAXN * MAXF];     // post BN+ELU (next layer input)
__device__ float g_agg[MAXN * MAXF];   // aggregation output
__device__ float g_as[MAXN * MAXH];
__device__ float g_ad[MAXN * MAXH];
__device__ float g_w[MAXE * MAXH];     // per-edge exp weights (CSR order)
__device__ float g_invs[MAXN * MAXH];  // 1 / softmax denominator
__device__ int   g_deg[MAXN];
__device__ int   g_rowptr[MAXN + 1];
__device__ int   g_cursor[MAXN];
__device__ int   g_srcs[MAXE];
__device__ float g_colsum[MAXF];
__device__ float g_colsq[MAXF];
__device__ int   g_bsums[64];

// ---------------------------------------------------------------------------
// CSR build
// ---------------------------------------------------------------------------
__global__ void k_zero_int(int* p, int n) {
    int i = blockIdx.x * blockDim.x + threadIdx.x;
    if (i < n) p[i] = 0;
}

__global__ void k_hist(const int* __restrict__ ei, int E, int N, int* __restrict__ deg) {
    int e = blockIdx.x * blockDim.x + threadIdx.x;
    if (e >= E + N) return;
    int dst = (e < E) ? ei[E + e] : (e - E);
    atomicAdd(&deg[dst], 1);
}

__global__ void k_scan1(const int* __restrict__ deg, int* __restrict__ rowptr,
                        int* __restrict__ bsums, int n) {
    __shared__ int sh[SCAN_B];
    int i = blockIdx.x * SCAN_B + threadIdx.x;
    int v = (i < n) ? deg[i] : 0;
    sh[threadIdx.x] = v;
    __syncthreads();
    for (int off = 1; off < SCAN_B; off <<= 1) {
        int t = 0;
        if ((int)threadIdx.x >= off) t = sh[threadIdx.x - off];
        __syncthreads();
        sh[threadIdx.x] += t;
        __syncthreads();
    }
    if (i < n) rowptr[i] = sh[threadIdx.x] - v;  // exclusive within block
    if (threadIdx.x == SCAN_B - 1) bsums[blockIdx.x] = sh[SCAN_B - 1];
}

__global__ void k_scan2(int* bsums, int nb) {
    if (threadIdx.x == 0) {
        int run = 0;
        for (int i = 0; i < nb; i++) { int v = bsums[i]; bsums[i] = run; run += v; }
    }
}

__global__ void k_scan3(int* __restrict__ rowptr, const int* __restrict__ bsums,
                        int n, int etot, int* __restrict__ cursor) {
    int i = blockIdx.x * blockDim.x + threadIdx.x;
    if (i < n) {
        int v = rowptr[i] + bsums[i / SCAN_B];
        rowptr[i] = v;
        cursor[i] = v;
    }
    if (i == 0) rowptr[n] = etot;
}

__global__ void k_scatter(const int* __restrict__ ei, int E, int N,
                          int* __restrict__ cursor, int* __restrict__ srcs) {
    int e = blockIdx.x * blockDim.x + threadIdx.x;
    if (e >= E + N) return;
    int src, dst;
    if (e < E) { src = ei[e]; dst = ei[E + e]; }
    else       { src = dst = e - E; }
    int p = atomicAdd(&cursor[dst], 1);
    srcs[p] = src;
}

// ---------------------------------------------------------------------------
// SGEMM: C[M,Nn] = A[M,K] * B[K,Nn]. BM=BN=64, BK=16, 256 threads, 4x4/thread.
// ---------------------------------------------------------------------------
__global__ void k_sgemm(const float* __restrict__ A, const float* __restrict__ B,
                        float* __restrict__ C, int M, int K, int Nn) {
    __shared__ float As[16][68];
    __shared__ float Bs[16][68];
    int tid = threadIdx.x;
    int tx = tid & 15;       // 0..15
    int ty = tid >> 4;       // 0..15
    int row0 = blockIdx.y * 64;
    int col0 = blockIdx.x * 64;

    int arow = tid >> 2;           // 0..63
    int acol = (tid & 3) * 4;      // 0,4,8,12
    int brow = tid >> 4;           // 0..15
    int bcol = (tid & 15) * 4;     // 0..60

    float acc[4][4];
#pragma unroll
    for (int i = 0; i < 4; i++)
#pragma unroll
        for (int j = 0; j < 4; j++) acc[i][j] = 0.f;

    for (int k0 = 0; k0 < K; k0 += 16) {
        float4 av = make_float4(0.f, 0.f, 0.f, 0.f);
        if (row0 + arow < M)
            av = *(const float4*)(A + (size_t)(row0 + arow) * K + k0 + acol);
        As[acol + 0][arow] = av.x;
        As[acol + 1][arow] = av.y;
        As[acol + 2][arow] = av.z;
        As[acol + 3][arow] = av.w;

        float4 bv = make_float4(0.f, 0.f, 0.f, 0.f);
        if (col0 + bcol < Nn)
            bv = *(const float4*)(B + (size_t)(k0 + brow) * Nn + col0 + bcol);
        Bs[brow][bcol + 0] = bv.x;
        Bs[brow][bcol + 1] = bv.y;
        Bs[brow][bcol + 2] = bv.z;
        Bs[brow][bcol + 3] = bv.w;
        __syncthreads();

#pragma unroll
        for (int kk = 0; kk < 16; kk++) {
            float4 a4 = *(const float4*)&As[kk][ty * 4];
            float4 b4 = *(const float4*)&Bs[kk][tx * 4];
            float a[4] = {a4.x, a4.y, a4.z, a4.w};
            float b[4] = {b4.x, b4.y, b4.z, b4.w};
#pragma unroll
            for (int i = 0; i < 4; i++)
#pragma unroll
                for (int j = 0; j < 4; j++) acc[i][j] += a[i] * b[j];
        }
        __syncthreads();
    }

#pragma unroll
    for (int i = 0; i < 4; i++) {
        int r = row0 + ty * 4 + i;
        if (r >= M) break;
#pragma unroll
        for (int j = 0; j < 4; j++) {
            int c = col0 + tx * 4 + j;
            if (c < Nn) C[(size_t)r * Nn + c] = acc[i][j];
        }
    }
}

// ---------------------------------------------------------------------------
// Attention coefficients a_s[n,h] = <h[n,h,:], att_src[h,:]>, same for a_d.
// One warp per (n,h) pair.
// ---------------------------------------------------------------------------
__global__ void k_attcoef(const float* __restrict__ h, const float* __restrict__ as,
                          const float* __restrict__ ad, float* __restrict__ out_s,
                          float* __restrict__ out_d, int N, int H, int C) {
    int wid = blockIdx.x * (blockDim.x >> 5) + (threadIdx.x >> 5);
    int lane = threadIdx.x & 31;
    if (wid >= N * H) return;
    int n = wid / H;
    int hh = wid - n * H;
    int F = H * C;
    const float* hr = h + (size_t)n * F + hh * C;
    const float* asr = as + hh * C;
    const float* adr = ad + hh * C;
    float s = 0.f, d = 0.f;
    for (int c = lane; c < C; c += 32) {
        float v = hr[c];
        s += v * asr[c];
        d += v * adr[c];
    }
#pragma unroll
    for (int o = 16; o; o >>= 1) {
        s += __shfl_xor_sync(0xffffffffu, s, o);
        d += __shfl_xor_sync(0xffffffffu, d, o);
    }
    if (lane == 0) {
        out_s[wid] = s;
        out_d[wid] = d;
    }
}

// ---------------------------------------------------------------------------
// Per-node segment softmax. Block = 32*H threads; warp h handles head h.
// Pass 1: max; pass 2: exp + sum, store exp weights.
// ---------------------------------------------------------------------------
__global__ void k_attn(const float* __restrict__ a_s, const float* __restrict__ a_d,
                       const int* __restrict__ rowptr, const int* __restrict__ srcs,
                       float* __restrict__ w, float* __restrict__ invs, int H) {
    int n = blockIdx.x;
    int hh = threadIdx.x >> 5;
    int lane = threadIdx.x & 31;
    int st = rowptr[n], en = rowptr[n + 1];
    float adv = a_d[n * H + hh];

    float mx = -1e30f;
    for (int i = st + lane; i < en; i += 32) {
        float v = a_s[srcs[i] * H + hh] + adv;
        v = v >= 0.f ? v : 0.2f * v;
        mx = fmaxf(mx, v);
    }
#pragma unroll
    for (int o = 16; o; o >>= 1) mx = fmaxf(mx, __shfl_xor_sync(0xffffffffu, mx, o));

    float sum = 0.f;
    for (int i = st + lane; i < en; i += 32) {
        float v = a_s[srcs[i] * H + hh] + adv;
        v = v >= 0.f ? v : 0.2f * v;
        float ex = expf(v - mx);
        w[i * H + hh] = ex;
        sum += ex;
    }
#pragma unroll
    for (int o = 16; o; o >>= 1) sum += __shfl_xor_sync(0xffffffffu, sum, o);
    if (lane == 0) invs[n * H + hh] = 1.f / sum;
}

// ---------------------------------------------------------------------------
// Aggregation: out[n,f] = sum_{e in CSR[n]} h[src_e, f] * w[e,head(f)]*invs[n,head(f)]
// Block per node. Up to 2 features per thread.
// ---------------------------------------------------------------------------
__global__ void k_agg(const float* __restrict__ h, const float* __restrict__ w,
                      const float* __restrict__ invs, const int* __restrict__ rowptr,
                      const int* __restrict__ srcs, const float* __restrict__ bias,
                      float* __restrict__ out, int H, int C, int F) {
    int n = blockIdx.x;
    int T = blockDim.x;
    int f0 = threadIdx.x;
    int f1 = f0 + T;
    if (f0 >= F) return;
    bool has1 = f1 < F;
    int h0 = f0 / C;
    int h1 = has1 ? f1 / C : 0;
    int st = rowptr[n], en = rowptr[n + 1];
    float ci0 = invs[n * H + h0];
    float ci1 = has1 ? invs[n * H + h1] : 0.f;
    float acc0 = 0.f, acc1 = 0.f;
    for (int e = st; e < en; e++) {
        int s = srcs[e];
        const float* hr = h + (size_t)s * F;
        float a0 = w[e * H + h0] * ci0;
        acc0 += hr[f0] * a0;
        if (has1) {
            float a1 = w[e * H + h1] * ci1;
            acc1 += hr[f1] * a1;
        }
    }
    out[(size_t)n * F + f0] = acc0 + bias[f0];
    if (has1) out[(size_t)n * F + f1] = acc1 + bias[f1];
}

// ---------------------------------------------------------------------------
// BatchNorm (biased var) + ELU
// ---------------------------------------------------------------------------
__global__ void k_zero_f2(float* a, float* b, int n) {
    int i = blockIdx.x * blockDim.x + threadIdx.x;
    if (i < n) { a[i] = 0.f; b[i] = 0.f; }
}

__global__ void k_bnstats(const float* __restrict__ x, float* __restrict__ csum,
                          float* __restrict__ csq, int N, int F) {
    int c = threadIdx.x;  // blockDim.x == F
    float s = 0.f, sq = 0.f;
    for (int r = blockIdx.x; r < N; r += gridDim.x) {
        float v = x[(size_t)r * F + c];
        s += v;
        sq += v * v;
    }
    atomicAdd(&csum[c], s);
    atomicAdd(&csq[c], sq);
}

__global__ void k_bnapply(const float* __restrict__ in, float* __restrict__ out,
                          const float* __restrict__ csum, const float* __restrict__ csq,
                          const float* __restrict__ gamma, const float* __restrict__ beta,
                          int N, int F) {
    int idx = blockIdx.x * blockDim.x + threadIdx.x;
    if (idx >= N * F) return;
    int c = idx % F;
    float invN = 1.f / (float)N;
    float mean = csum[c] * invN;
    float var = csq[c] * invN - mean * mean;
    float v = (in[idx] - mean) * rsqrtf(var + 1e-5f) * gamma[c] + beta[c];
    out[idx] = v > 0.f ? v : (expf(v) - 1.f);
}

// ---------------------------------------------------------------------------
// log_softmax over 16 classes, one thread per node
// ---------------------------------------------------------------------------
__global__ void k_logsoftmax16(const float* __restrict__ in, float* __restrict__ out, int N) {
    int n = blockIdx.x * blockDim.x + threadIdx.x;
    if (n >= N) return;
    const float* r = in + n * 16;
    float mx = r[0];
#pragma unroll
    for (int j = 1; j < 16; j++) mx = fmaxf(mx, r[j]);
    float s = 0.f;
#pragma unroll
    for (int j = 0; j < 16; j++) s += expf(r[j] - mx);
    float ls = logf(s) + mx;
    float* o = out + n * 16;
#pragma unroll
    for (int j = 0; j < 16; j++) o[j] = r[j] - ls;
}

// ---------------------------------------------------------------------------
// Host orchestration
// ---------------------------------------------------------------------------
extern "C" void kernel_launch(void* const* d_in, const int* in_sizes, int n_in,
                              void* d_out, int out_size) {
    const float* x = (const float*)d_in[0];
    const int* ei = (const int*)d_in[1];
    int N = in_sizes[0] / 512;
    int E = in_sizes[1] / 2;
    int Etot = E + N;

    float *p_h, *p_y, *p_agg, *p_as, *p_ad, *p_w, *p_invs, *p_csum, *p_csq;
    int *p_deg, *p_rowptr, *p_cursor, *p_srcs, *p_bsums;
    cudaGetSymbolAddress((void**)&p_h, g_h);
    cudaGetSymbolAddress((void**)&p_y, g_y);
    cudaGetSymbolAddress((void**)&p_agg, g_agg);
    cudaGetSymbolAddress((void**)&p_as, g_as);
    cudaGetSymbolAddress((void**)&p_ad, g_ad);
    cudaGetSymbolAddress((void**)&p_w, g_w);
    cudaGetSymbolAddress((void**)&p_invs, g_invs);
    cudaGetSymbolAddress((void**)&p_csum, g_colsum);
    cudaGetSymbolAddress((void**)&p_csq, g_colsq);
    cudaGetSymbolAddress((void**)&p_deg, g_deg);
    cudaGetSymbolAddress((void**)&p_rowptr, g_rowptr);
    cudaGetSymbolAddress((void**)&p_cursor, g_cursor);
    cudaGetSymbolAddress((void**)&p_srcs, g_srcs);
    cudaGetSymbolAddress((void**)&p_bsums, g_bsums);

    // ---- CSR build ----
    k_zero_int<<<(N + 255) / 256, 256>>>(p_deg, N);
    k_hist<<<(Etot + 255) / 256, 256>>>(ei, E, N, p_deg);
    int nblk = (N + SCAN_B - 1) / SCAN_B;
    k_scan1<<<nblk, SCAN_B>>>(p_deg, p_rowptr, p_bsums, N);
    k_scan2<<<1, 32>>>(p_bsums, nblk);
    k_scan3<<<(N + 255) / 256, 256>>>(p_rowptr, p_bsums, N, Etot, p_cursor);
    k_scatter<<<(Etot + 255) / 256, 256>>>(ei, E, N, p_cursor, p_srcs);

    // layer configs: (Fin, H, C), input order: W, as, ad, b [, g, be]
    struct Cfg { int Fin, H, C, iW; bool bn; };
    const Cfg cfgs[4] = {
        {512, 8, 64, 2, true},
        {512, 4, 64, 8, true},
        {256, 2, 64, 14, true},
        {128, 1, 16, 20, false},
    };

    const float* in = x;
    for (int li = 0; li < 4; li++) {
        const Cfg& cf = cfgs[li];
        int F = cf.H * cf.C;
        const float* W  = (const float*)d_in[cf.iW + 0];
        const float* as = (const float*)d_in[cf.iW + 1];
        const float* ad = (const float*)d_in[cf.iW + 2];
        const float* bi = (const float*)d_in[cf.iW + 3];

        // GEMM: g_h = in @ W
        dim3 ggrid((F + 63) / 64, (N + 63) / 64);
        k_sgemm<<<ggrid, 256>>>(in, W, p_h, N, cf.Fin, F);

        // attention coefficients
        int pairs = N * cf.H;
        k_attcoef<<<(pairs + 3) / 4, 128>>>(p_h, as, ad, p_as, p_ad, N, cf.H, cf.C);

        // segment softmax
        k_attn<<<N, 32 * cf.H>>>(p_as, p_ad, p_rowptr, p_srcs, p_w, p_invs, cf.H);

        // aggregation (+bias)
        int T = F <= 256 ? (F < 32 ? 32 : F) : 256;
        k_agg<<<N, T>>>(p_h, p_w, p_invs, p_rowptr, p_srcs, bi, p_agg, cf.H, cf.C, F);

        if (cf.bn) {
            const float* gamma = (const float*)d_in[cf.iW + 4];
            const float* beta  = (const float*)d_in[cf.iW + 5];
            k_zero_f2<<<1, F>>>(p_csum, p_csq, F);
            k_bnstats<<<240, F>>>(p_agg, p_csum, p_csq, N, F);
            k_bnapply<<<(N * F + 255) / 256, 256>>>(p_agg, p_y, p_csum, p_csq, gamma, beta, N, F);
            in = p_y;
        } else {
            k_logsoftmax16<<<(N + 255) / 256, 256>>>(p_agg, (float*)d_out, N);
        }
    }
}

// round 3
// speedup vs baseline: 1.3562x; 1.3562x over previous
#include <cuda_runtime.h>
#include <cuda_bf16.h>
#include <cstdint>
#include <math.h>

// ---------------------------------------------------------------------------
// GAT 4-layer network.
//   - CSR build (dst-sorted) once per call
//   - Layers 1-3: split-bf16 HMMA GEMM (mma.sync m16n8k16) with cp.async
//     double buffering; layer 4: exact fp32 SIMT GEMM (tiny).
//   - attention coefficients, per-node segment softmax, per-node aggregation,
//     BN+ELU (fused with bf16 hi/lo re-split), log_softmax.
// All scratch in __device__ globals (no allocation).
// ---------------------------------------------------------------------------

#define MAXN 20000
#define MAXE 360000
#define MAXF 512
#define MAXH 8
#define SCAN_B 512

__device__ float g_h[MAXN * MAXF];
__device__ float g_y[MAXN * MAXF];
__device__ float g_agg[MAXN * MAXF];
__device__ float g_as[MAXN * MAXH];
__device__ float g_ad[MAXN * MAXH];
__device__ float g_w[MAXE * MAXH];
__device__ float g_invs[MAXN * MAXH];
__device__ int   g_deg[MAXN];
__device__ int   g_rowptr[MAXN + 1];
__device__ int   g_cursor[MAXN];
__device__ int   g_srcs[MAXE];
__device__ float g_colsum[MAXF];
__device__ float g_colsq[MAXF];
__device__ int   g_bsums[64];
// split-bf16 GEMM operands
__device__ __nv_bfloat16 g_ahi[MAXN * MAXF];
__device__ __nv_bfloat16 g_alo[MAXN * MAXF];
__device__ __nv_bfloat16 g_bhi[MAXF * MAXF];   // W, [K,N] layout (no transpose)
__device__ __nv_bfloat16 g_blo[MAXF * MAXF];

// ---------------------------------------------------------------------------
// PTX helpers (sm_80+ baseline: mma.sync / ldmatrix / cp.async)
// ---------------------------------------------------------------------------
__device__ __forceinline__ uint32_t smem_to_u32(const void* p) {
    uint32_t a;
    asm("{ .reg .u64 t; cvta.to.shared.u64 t, %1; cvt.u32.u64 %0, t; }" : "=r"(a) : "l"(p));
    return a;
}
__device__ __forceinline__ void cp16(uint32_t s, const void* g) {
    asm volatile("cp.async.cg.shared.global [%0], [%1], 16;" :: "r"(s), "l"(g));
}
__device__ __forceinline__ void ldsm_x4(uint32_t* r, uint32_t addr) {
    asm volatile("ldmatrix.sync.aligned.m8n8.x4.shared.b16 {%0,%1,%2,%3}, [%4];"
        : "=r"(r[0]), "=r"(r[1]), "=r"(r[2]), "=r"(r[3]) : "r"(addr));
}
__device__ __forceinline__ void ldsm_x4_t(uint32_t* r, uint32_t addr) {
    asm volatile("ldmatrix.sync.aligned.m8n8.x4.trans.shared.b16 {%0,%1,%2,%3}, [%4];"
        : "=r"(r[0]), "=r"(r[1]), "=r"(r[2]), "=r"(r[3]) : "r"(addr));
}
__device__ __forceinline__ void mma16816(float* c, const uint32_t* a, const uint32_t* b) {
    asm volatile("mma.sync.aligned.m16n8k16.row.col.f32.bf16.bf16.f32 "
        "{%0,%1,%2,%3}, {%4,%5,%6,%7}, {%8,%9}, {%0,%1,%2,%3};"
        : "+f"(c[0]), "+f"(c[1]), "+f"(c[2]), "+f"(c[3])
        : "r"(a[0]), "r"(a[1]), "r"(a[2]), "r"(a[3]), "r"(b[0]), "r"(b[1]));
}

// ---------------------------------------------------------------------------
// CSR build
// ---------------------------------------------------------------------------
__global__ void k_zero_int(int* p, int n) {
    int i = blockIdx.x * blockDim.x + threadIdx.x;
    if (i < n) p[i] = 0;
}

__global__ void k_hist(const int* __restrict__ ei, int E, int N, int* __restrict__ deg) {
    int e = blockIdx.x * blockDim.x + threadIdx.x;
    if (e >= E + N) return;
    int dst = (e < E) ? ei[E + e] : (e - E);
    atomicAdd(&deg[dst], 1);
}

__global__ void k_scan1(const int* __restrict__ deg, int* __restrict__ rowptr,
                        int* __restrict__ bsums, int n) {
    __shared__ int sh[SCAN_B];
    int i = blockIdx.x * SCAN_B + threadIdx.x;
    int v = (i < n) ? deg[i] : 0;
    sh[threadIdx.x] = v;
    __syncthreads();
    for (int off = 1; off < SCAN_B; off <<= 1) {
        int t = 0;
        if ((int)threadIdx.x >= off) t = sh[threadIdx.x - off];
        __syncthreads();
        sh[threadIdx.x] += t;
        __syncthreads();
    }
    if (i < n) rowptr[i] = sh[threadIdx.x] - v;
    if (threadIdx.x == SCAN_B - 1) bsums[blockIdx.x] = sh[SCAN_B - 1];
}

__global__ void k_scan2(int* bsums, int nb) {
    if (threadIdx.x == 0) {
        int run = 0;
        for (int i = 0; i < nb; i++) { int v = bsums[i]; bsums[i] = run; run += v; }
    }
}

__global__ void k_scan3(int* __restrict__ rowptr, const int* __restrict__ bsums,
                        int n, int etot, int* __restrict__ cursor) {
    int i = blockIdx.x * blockDim.x + threadIdx.x;
    if (i < n) {
        int v = rowptr[i] + bsums[i / SCAN_B];
        rowptr[i] = v;
        cursor[i] = v;
    }
    if (i == 0) rowptr[n] = etot;
}

__global__ void k_scatter(const int* __restrict__ ei, int E, int N,
                          int* __restrict__ cursor, int* __restrict__ srcs) {
    int e = blockIdx.x * blockDim.x + threadIdx.x;
    if (e >= E + N) return;
    int src, dst;
    if (e < E) { src = ei[e]; dst = ei[E + e]; }
    else       { src = dst = e - E; }
    int p = atomicAdd(&cursor[dst], 1);
    srcs[p] = src;
}

// ---------------------------------------------------------------------------
// fp32 -> (bf16 hi, bf16 lo) split (elementwise, layout-preserving)
// ---------------------------------------------------------------------------
__global__ void k_split(const float* __restrict__ x, __nv_bfloat16* __restrict__ hi,
                        __nv_bfloat16* __restrict__ lo, int n) {
    int i = (blockIdx.x * blockDim.x + threadIdx.x) * 4;
    if (i >= n) return;
    float4 v = *(const float4*)(x + i);
    __nv_bfloat16 h0 = __float2bfloat16(v.x), h1 = __float2bfloat16(v.y);
    __nv_bfloat16 h2 = __float2bfloat16(v.z), h3 = __float2bfloat16(v.w);
    __nv_bfloat16 l0 = __float2bfloat16(v.x - __bfloat162float(h0));
    __nv_bfloat16 l1 = __float2bfloat16(v.y - __bfloat162float(h1));
    __nv_bfloat16 l2 = __float2bfloat16(v.z - __bfloat162float(h2));
    __nv_bfloat16 l3 = __float2bfloat16(v.w - __bfloat162float(h3));
    __nv_bfloat162* ph = (__nv_bfloat162*)(hi + i);
    __nv_bfloat162* pl = (__nv_bfloat162*)(lo + i);
    ph[0] = __nv_bfloat162(h0, h1); ph[1] = __nv_bfloat162(h2, h3);
    pl[0] = __nv_bfloat162(l0, l1); pl[1] = __nv_bfloat162(l2, l3);
}

// ---------------------------------------------------------------------------
// split-bf16 HMMA GEMM: C[M,Nn] = A[M,K] @ B[K,Nn]
// A hi/lo: [M,K] bf16; B hi/lo: [K,Nn] bf16.
// Tile 128x128x32, 256 threads (8 warps, 2x4), warp tile 64x32.
// cp.async double buffered. C = Ahi*Bhi + Ahi*Blo + Alo*Bhi (fp32 acc).
// Requires: K % 32 == 0, Nn % 128 == 0.
// ---------------------------------------------------------------------------
#define STAGE_BYTES 37888  // Ahi 10240 + Alo 10240 + Bhi 8704 + Blo 8704
#define OFF_ALO 10240
#define OFF_BHI 20480
#define OFF_BLO 29184
#define MMA_SMEM (2 * STAGE_BYTES)

__global__ void __launch_bounds__(256) k_mma_gemm(
    const __nv_bfloat16* __restrict__ Ahi, const __nv_bfloat16* __restrict__ Alo,
    const __nv_bfloat16* __restrict__ Bhi, const __nv_bfloat16* __restrict__ Blo,
    float* __restrict__ C, int M, int K, int Nn) {
    extern __shared__ char smem[];
    uint32_t sbu = smem_to_u32(smem);
    int tid = threadIdx.x, lane = tid & 31, wid = tid >> 5;
    int wm = wid & 1, wn = wid >> 1;        // 2 x 4 warp grid
    int row0 = blockIdx.y * 128, col0 = blockIdx.x * 128;

    float c[4][4][4];
#pragma unroll
    for (int i = 0; i < 4; i++)
#pragma unroll
        for (int j = 0; j < 4; j++) {
            c[i][j][0] = 0.f; c[i][j][1] = 0.f; c[i][j][2] = 0.f; c[i][j][3] = 0.f;
        }

    int nch = K >> 5;

    auto issue = [&](int ch) {
        int st = ch & 1;
        uint32_t sb = sbu + st * STAGE_BYTES;
        int k0 = ch << 5;
#pragma unroll
        for (int i = 0; i < 2; i++) {
            int g = tid + i * 256;
            // A tiles: 128 rows x 32 cols
            int r = g >> 2, c8 = (g & 3) << 3;
            int row = row0 + r;
            if (row >= M) row = M - 1;  // clamp (values unused; rows not stored)
            size_t ga = (size_t)row * K + k0 + c8;
            uint32_t sa = sb + r * 80 + (c8 << 1);
            cp16(sa, Ahi + ga);
            cp16(sa + OFF_ALO, Alo + ga);
            // B tiles: 32 rows x 128 cols
            int rb = g >> 4, cb = (g & 15) << 3;
            size_t gb = (size_t)(k0 + rb) * Nn + col0 + cb;
            uint32_t sB = sb + OFF_BHI + rb * 272 + (cb << 1);
            cp16(sB, Bhi + gb);
            cp16(sB + (OFF_BLO - OFF_BHI), Blo + gb);
        }
        asm volatile("cp.async.commit_group;" ::: "memory");
    };

    issue(0);
    for (int ch = 0; ch < nch; ch++) {
        if (ch + 1 < nch) {
            issue(ch + 1);
            asm volatile("cp.async.wait_group 1;" ::: "memory");
        } else {
            asm volatile("cp.async.wait_group 0;" ::: "memory");
        }
        __syncthreads();

        uint32_t sb = sbu + (ch & 1) * STAGE_BYTES;
#pragma unroll
        for (int kk2 = 0; kk2 < 2; kk2++) {
            int kk = kk2 << 4;
            uint32_t ah[4][4], al[4][4], bh[2][4], bl[2][4];
#pragma unroll
            for (int mt = 0; mt < 4; mt++) {
                uint32_t aoff = sb + (uint32_t)(wm * 64 + mt * 16 + (lane & 15)) * 80
                              + ((kk + ((lane >> 4) << 3)) << 1);
                ldsm_x4(ah[mt], aoff);
                ldsm_x4(al[mt], aoff + OFF_ALO);
            }
#pragma unroll
            for (int nt2 = 0; nt2 < 2; nt2++) {
                uint32_t boff = sb + OFF_BHI + (uint32_t)(kk + (lane & 15)) * 272
                              + ((wn * 32 + nt2 * 16 + ((lane >> 4) << 3)) << 1);
                ldsm_x4_t(bh[nt2], boff);
                ldsm_x4_t(bl[nt2], boff + (OFF_BLO - OFF_BHI));
            }
#pragma unroll
            for (int mt = 0; mt < 4; mt++)
#pragma unroll
                for (int nt = 0; nt < 4; nt++) {
                    const uint32_t* bhp = &bh[nt >> 1][(nt & 1) << 1];
                    const uint32_t* blp = &bl[nt >> 1][(nt & 1) << 1];
                    mma16816(c[mt][nt], ah[mt], bhp);
                    mma16816(c[mt][nt], ah[mt], blp);
                    mma16816(c[mt][nt], al[mt], bhp);
                }
        }
        __syncthreads();
    }

    // epilogue
#pragma unroll
    for (int mt = 0; mt < 4; mt++) {
        int r = row0 + wm * 64 + mt * 16 + (lane >> 2);
#pragma unroll
        for (int nt = 0; nt < 4; nt++) {
            int col = col0 + wn * 32 + nt * 8 + ((lane & 3) << 1);
            if (r < M) {
                float2 v = make_float2(c[mt][nt][0], c[mt][nt][1]);
                *(float2*)(C + (size_t)r * Nn + col) = v;
            }
            if (r + 8 < M) {
                float2 v = make_float2(c[mt][nt][2], c[mt][nt][3]);
                *(float2*)(C + (size_t)(r + 8) * Nn + col) = v;
            }
        }
    }
}

// ---------------------------------------------------------------------------
// fp32 SIMT SGEMM (layer 4 only: tiny). BM=BN=64, BK=16.
// ---------------------------------------------------------------------------
__global__ void k_sgemm(const float* __restrict__ A, const float* __restrict__ B,
                        float* __restrict__ C, int M, int K, int Nn) {
    __shared__ float As[16][68];
    __shared__ float Bs[16][68];
    int tid = threadIdx.x;
    int tx = tid & 15;
    int ty = tid >> 4;
    int row0 = blockIdx.y * 64;
    int col0 = blockIdx.x * 64;

    int arow = tid >> 2;
    int acol = (tid & 3) * 4;
    int brow = tid >> 4;
    int bcol = (tid & 15) * 4;

    float acc[4][4];
#pragma unroll
    for (int i = 0; i < 4; i++)
#pragma unroll
        for (int j = 0; j < 4; j++) acc[i][j] = 0.f;

    for (int k0 = 0; k0 < K; k0 += 16) {
        float4 av = make_float4(0.f, 0.f, 0.f, 0.f);
        if (row0 + arow < M)
            av = *(const float4*)(A + (size_t)(row0 + arow) * K + k0 + acol);
        As[acol + 0][arow] = av.x;
        As[acol + 1][arow] = av.y;
        As[acol + 2][arow] = av.z;
        As[acol + 3][arow] = av.w;

        float4 bv = make_float4(0.f, 0.f, 0.f, 0.f);
        if (col0 + bcol < Nn)
            bv = *(const float4*)(B + (size_t)(k0 + brow) * Nn + col0 + bcol);
        Bs[brow][bcol + 0] = bv.x;
        Bs[brow][bcol + 1] = bv.y;
        Bs[brow][bcol + 2] = bv.z;
        Bs[brow][bcol + 3] = bv.w;
        __syncthreads();

#pragma unroll
        for (int kk = 0; kk < 16; kk++) {
            float4 a4 = *(const float4*)&As[kk][ty * 4];
            float4 b4 = *(const float4*)&Bs[kk][tx * 4];
            float a[4] = {a4.x, a4.y, a4.z, a4.w};
            float b[4] = {b4.x, b4.y, b4.z, b4.w};
#pragma unroll
            for (int i = 0; i < 4; i++)
#pragma unroll
                for (int j = 0; j < 4; j++) acc[i][j] += a[i] * b[j];
        }
        __syncthreads();
    }

#pragma unroll
    for (int i = 0; i < 4; i++) {
        int r = row0 + ty * 4 + i;
        if (r >= M) break;
#pragma unroll
        for (int j = 0; j < 4; j++) {
            int cc = col0 + tx * 4 + j;
            if (cc < Nn) C[(size_t)r * Nn + cc] = acc[i][j];
        }
    }
}

// ---------------------------------------------------------------------------
// Attention coefficients
// ---------------------------------------------------------------------------
__global__ void k_attcoef(const float* __restrict__ h, const float* __restrict__ as,
                          const float* __restrict__ ad, float* __restrict__ out_s,
                          float* __restrict__ out_d, int N, int H, int C) {
    int wid = blockIdx.x * (blockDim.x >> 5) + (threadIdx.x >> 5);
    int lane = threadIdx.x & 31;
    if (wid >= N * H) return;
    int n = wid / H;
    int hh = wid - n * H;
    int F = H * C;
    const float* hr = h + (size_t)n * F + hh * C;
    const float* asr = as + hh * C;
    const float* adr = ad + hh * C;
    float s = 0.f, d = 0.f;
    for (int c = lane; c < C; c += 32) {
        float v = hr[c];
        s += v * asr[c];
        d += v * adr[c];
    }
#pragma unroll
    for (int o = 16; o; o >>= 1) {
        s += __shfl_xor_sync(0xffffffffu, s, o);
        d += __shfl_xor_sync(0xffffffffu, d, o);
    }
    if (lane == 0) {
        out_s[wid] = s;
        out_d[wid] = d;
    }
}

// ---------------------------------------------------------------------------
// Per-node segment softmax
// ---------------------------------------------------------------------------
__global__ void k_attn(const float* __restrict__ a_s, const float* __restrict__ a_d,
                       const int* __restrict__ rowptr, const int* __restrict__ srcs,
                       float* __restrict__ w, float* __restrict__ invs, int H) {
    int n = blockIdx.x;
    int hh = threadIdx.x >> 5;
    int lane = threadIdx.x & 31;
    int st = rowptr[n], en = rowptr[n + 1];
    float adv = a_d[n * H + hh];

    float mx = -1e30f;
    for (int i = st + lane; i < en; i += 32) {
        float v = a_s[srcs[i] * H + hh] + adv;
        v = v >= 0.f ? v : 0.2f * v;
        mx = fmaxf(mx, v);
    }
#pragma unroll
    for (int o = 16; o; o >>= 1) mx = fmaxf(mx, __shfl_xor_sync(0xffffffffu, mx, o));

    float sum = 0.f;
    for (int i = st + lane; i < en; i += 32) {
        float v = a_s[srcs[i] * H + hh] + adv;
        v = v >= 0.f ? v : 0.2f * v;
        float ex = expf(v - mx);
        w[i * H + hh] = ex;
        sum += ex;
    }
#pragma unroll
    for (int o = 16; o; o >>= 1) sum += __shfl_xor_sync(0xffffffffu, sum, o);
    if (lane == 0) invs[n * H + hh] = 1.f / sum;
}

// ---------------------------------------------------------------------------
// Aggregation
// ---------------------------------------------------------------------------
__global__ void k_agg(const float* __restrict__ h, const float* __restrict__ w,
                      const float* __restrict__ invs, const int* __restrict__ rowptr,
                      const int* __restrict__ srcs, const float* __restrict__ bias,
                      float* __restrict__ out, int H, int C, int F) {
    int n = blockIdx.x;
    int T = blockDim.x;
    int f0 = threadIdx.x;
    int f1 = f0 + T;
    if (f0 >= F) return;
    bool has1 = f1 < F;
    int h0 = f0 / C;
    int h1 = has1 ? f1 / C : 0;
    int st = rowptr[n], en = rowptr[n + 1];
    float ci0 = invs[n * H + h0];
    float ci1 = has1 ? invs[n * H + h1] : 0.f;
    float acc0 = 0.f, acc1 = 0.f;
    for (int e = st; e < en; e++) {
        int s = srcs[e];
        const float* hr = h + (size_t)s * F;
        float a0 = w[e * H + h0] * ci0;
        acc0 += hr[f0] * a0;
        if (has1) {
            float a1 = w[e * H + h1] * ci1;
            acc1 += hr[f1] * a1;
        }
    }
    out[(size_t)n * F + f0] = acc0 + bias[f0];
    if (has1) out[(size_t)n * F + f1] = acc1 + bias[f1];
}

// ---------------------------------------------------------------------------
// BatchNorm + ELU (fused with bf16 hi/lo split of the output)
// ---------------------------------------------------------------------------
__global__ void k_zero_f2(float* a, float* b, int n) {
    int i = blockIdx.x * blockDim.x + threadIdx.x;
    if (i < n) { a[i] = 0.f; b[i] = 0.f; }
}

__global__ void k_bnstats(const float* __restrict__ x, float* __restrict__ csum,
                          float* __restrict__ csq, int N, int F) {
    int c = threadIdx.x;
    float s = 0.f, sq = 0.f;
    for (int r = blockIdx.x; r < N; r += gridDim.x) {
        float v = x[(size_t)r * F + c];
        s += v;
        sq += v * v;
    }
    atomicAdd(&csum[c], s);
    atomicAdd(&csq[c], sq);
}

__global__ void k_bnapply_split(const float* __restrict__ in, float* __restrict__ out,
                                __nv_bfloat16* __restrict__ hi, __nv_bfloat16* __restrict__ lo,
                                const float* __restrict__ csum, const float* __restrict__ csq,
                                const float* __restrict__ gamma, const float* __restrict__ beta,
                                int N, int F) {
    int idx = blockIdx.x * blockDim.x + threadIdx.x;
    if (idx >= N * F) return;
    int c = idx % F;
    float invN = 1.f / (float)N;
    float mean = csum[c] * invN;
    float var = csq[c] * invN - mean * mean;
    float v = (in[idx] - mean) * rsqrtf(var + 1e-5f) * gamma[c] + beta[c];
    v = v > 0.f ? v : (expf(v) - 1.f);
    out[idx] = v;
    __nv_bfloat16 h = __float2bfloat16(v);
    hi[idx] = h;
    lo[idx] = __float2bfloat16(v - __bfloat162float(h));
}

// ---------------------------------------------------------------------------
// log_softmax over 16 classes
// ---------------------------------------------------------------------------
__global__ void k_logsoftmax16(const float* __restrict__ in, float* __restrict__ out, int N) {
    int n = blockIdx.x * blockDim.x + threadIdx.x;
    if (n >= N) return;
    const float* r = in + n * 16;
    float mx = r[0];
#pragma unroll
    for (int j = 1; j < 16; j++) mx = fmaxf(mx, r[j]);
    float s = 0.f;
#pragma unroll
    for (int j = 0; j < 16; j++) s += expf(r[j] - mx);
    float ls = logf(s) + mx;
    float* o = out + n * 16;
#pragma unroll
    for (int j = 0; j < 16; j++) o[j] = r[j] - ls;
}

// ---------------------------------------------------------------------------
// Host orchestration
// ---------------------------------------------------------------------------
extern "C" void kernel_launch(void* const* d_in, const int* in_sizes, int n_in,
                              void* d_out, int out_size) {
    const float* x = (const float*)d_in[0];
    const int* ei = (const int*)d_in[1];
    int N = in_sizes[0] / 512;
    int E = in_sizes[1] / 2;
    int Etot = E + N;

    float *p_h, *p_y, *p_agg, *p_as, *p_ad, *p_w, *p_invs, *p_csum, *p_csq;
    int *p_deg, *p_rowptr, *p_cursor, *p_srcs, *p_bsums;
    __nv_bfloat16 *p_ahi, *p_alo, *p_bhi, *p_blo;
    cudaGetSymbolAddress((void**)&p_h, g_h);
    cudaGetSymbolAddress((void**)&p_y, g_y);
    cudaGetSymbolAddress((void**)&p_agg, g_agg);
    cudaGetSymbolAddress((void**)&p_as, g_as);
    cudaGetSymbolAddress((void**)&p_ad, g_ad);
    cudaGetSymbolAddress((void**)&p_w, g_w);
    cudaGetSymbolAddress((void**)&p_invs, g_invs);
    cudaGetSymbolAddress((void**)&p_csum, g_colsum);
    cudaGetSymbolAddress((void**)&p_csq, g_colsq);
    cudaGetSymbolAddress((void**)&p_deg, g_deg);
    cudaGetSymbolAddress((void**)&p_rowptr, g_rowptr);
    cudaGetSymbolAddress((void**)&p_cursor, g_cursor);
    cudaGetSymbolAddress((void**)&p_srcs, g_srcs);
    cudaGetSymbolAddress((void**)&p_bsums, g_bsums);
    cudaGetSymbolAddress((void**)&p_ahi, g_ahi);
    cudaGetSymbolAddress((void**)&p_alo, g_alo);
    cudaGetSymbolAddress((void**)&p_bhi, g_bhi);
    cudaGetSymbolAddress((void**)&p_blo, g_blo);

    cudaFuncSetAttribute(k_mma_gemm, cudaFuncAttributeMaxDynamicSharedMemorySize, MMA_SMEM);

    // ---- CSR build ----
    k_zero_int<<<(N + 255) / 256, 256>>>(p_deg, N);
    k_hist<<<(Etot + 255) / 256, 256>>>(ei, E, N, p_deg);
    int nblk = (N + SCAN_B - 1) / SCAN_B;
    k_scan1<<<nblk, SCAN_B>>>(p_deg, p_rowptr, p_bsums, N);
    k_scan2<<<1, 32>>>(p_bsums, nblk);
    k_scan3<<<(N + 255) / 256, 256>>>(p_rowptr, p_bsums, N, Etot, p_cursor);
    k_scatter<<<(Etot + 255) / 256, 256>>>(ei, E, N, p_cursor, p_srcs);

    struct Cfg { int Fin, H, C, iW; bool bn; };
    const Cfg cfgs[4] = {
        {512, 8, 64, 2, true},
        {512, 4, 64, 8, true},
        {256, 2, 64, 14, true},
        {128, 1, 16, 20, false},
    };

    const float* in = x;
    for (int li = 0; li < 4; li++) {
        const Cfg& cf = cfgs[li];
        int F = cf.H * cf.C;
        const float* W  = (const float*)d_in[cf.iW + 0];
        const float* as = (const float*)d_in[cf.iW + 1];
        const float* ad = (const float*)d_in[cf.iW + 2];
        const float* bi = (const float*)d_in[cf.iW + 3];

        if (li < 3) {
            // split inputs (layer 0 activation; later activations come
            // pre-split from k_bnapply_split) and W (elementwise, [K,N] kept)
            if (li == 0) {
                int nel = N * cf.Fin;
                k_split<<<(nel / 4 + 255) / 256, 256>>>(in, p_ahi, p_alo, nel);
            }
            int nw = cf.Fin * F;
            k_split<<<(nw / 4 + 255) / 256, 256>>>(W, p_bhi, p_blo, nw);
            dim3 gg(F / 128, (N + 127) / 128);
            k_mma_gemm<<<gg, 256, MMA_SMEM>>>(p_ahi, p_alo, p_bhi, p_blo, p_h, N, cf.Fin, F);
        } else {
            dim3 ggrid((F + 63) / 64, (N + 63) / 64);
            k_sgemm<<<ggrid, 256>>>(in, W, p_h, N, cf.Fin, F);
        }

        // attention coefficients
        int pairs = N * cf.H;
        k_attcoef<<<(pairs + 3) / 4, 128>>>(p_h, as, ad, p_as, p_ad, N, cf.H, cf.C);

        // segment softmax
        k_attn<<<N, 32 * cf.H>>>(p_as, p_ad, p_rowptr, p_srcs, p_w, p_invs, cf.H);

        // aggregation (+bias)
        int T = F <= 256 ? (F < 32 ? 32 : F) : 256;
        k_agg<<<N, T>>>(p_h, p_w, p_invs, p_rowptr, p_srcs, bi, p_agg, cf.H, cf.C, F);

        if (cf.bn) {
            const float* gamma = (const float*)d_in[cf.iW + 4];
            const float* beta  = (const float*)d_in[cf.iW + 5];
            k_zero_f2<<<1, F>>>(p_csum, p_csq, F);
            k_bnstats<<<240, F>>>(p_agg, p_csum, p_csq, N, F);
            k_bnapply_split<<<(N * F + 255) / 256, 256>>>(p_agg, p_y, p_ahi, p_alo,
                                                          p_csum, p_csq, gamma, beta, N, F);
            in = p_y;
        } else {
            k_logsoftmax16<<<(N + 255) / 256, 256>>>(p_agg, (float*)d_out, N);
        }
    }
}

// round 4
// speedup vs baseline: 1.8219x; 1.3434x over previous
#include <cuda_runtime.h>
#include <cuda_bf16.h>
#include <cstdint>
#include <math.h>

// ---------------------------------------------------------------------------
// GAT 4-layer network.
//   - CSR build (dst-sorted) once per call
//   - Layers 1-3: split-bf16 HMMA GEMM (mma.sync m16n8k16) with cp.async
//     double buffering; layer 4: exact fp32 SIMT GEMM (tiny).
//   - attention coefficients, per-node segment softmax (head-major edge buf),
//     per-node aggregation (float4 + unroll-4), BN+ELU (+bf16 re-split),
//     log_softmax.
// ---------------------------------------------------------------------------

#define MAXN 20000
#define MAXE 360000
#define MAXF 512
#define MAXH 8
#define SCAN_B 512

__device__ float g_h[MAXN * MAXF];
__device__ float g_y[MAXN * MAXF];
__device__ float g_agg[MAXN * MAXF];
__device__ float g_as[MAXN * MAXH];
__device__ float g_ad[MAXN * MAXH];
__device__ float g_w[MAXE * MAXH];     // head-major: [H][Etot]
__device__ float g_invs[MAXN * MAXH];
__device__ int   g_deg[MAXN];
__device__ int   g_rowptr[MAXN + 1];
__device__ int   g_cursor[MAXN];
__device__ int   g_srcs[MAXE];
__device__ float g_colsum[MAXF];
__device__ float g_colsq[MAXF];
__device__ int   g_bsums[64];
__device__ __nv_bfloat16 g_ahi[MAXN * MAXF];
__device__ __nv_bfloat16 g_alo[MAXN * MAXF];
__device__ __nv_bfloat16 g_bhi[MAXF * MAXF];
__device__ __nv_bfloat16 g_blo[MAXF * MAXF];

// ---------------------------------------------------------------------------
// PTX helpers (sm_80+ baseline: mma.sync / ldmatrix / cp.async)
// ---------------------------------------------------------------------------
__device__ __forceinline__ uint32_t smem_to_u32(const void* p) {
    uint32_t a;
    asm("{ .reg .u64 t; cvta.to.shared.u64 t, %1; cvt.u32.u64 %0, t; }" : "=r"(a) : "l"(p));
    return a;
}
__device__ __forceinline__ void cp16(uint32_t s, const void* g) {
    asm volatile("cp.async.cg.shared.global [%0], [%1], 16;" :: "r"(s), "l"(g));
}
__device__ __forceinline__ void ldsm_x4(uint32_t* r, uint32_t addr) {
    asm volatile("ldmatrix.sync.aligned.m8n8.x4.shared.b16 {%0,%1,%2,%3}, [%4];"
        : "=r"(r[0]), "=r"(r[1]), "=r"(r[2]), "=r"(r[3]) : "r"(addr));
}
__device__ __forceinline__ void ldsm_x4_t(uint32_t* r, uint32_t addr) {
    asm volatile("ldmatrix.sync.aligned.m8n8.x4.trans.shared.b16 {%0,%1,%2,%3}, [%4];"
        : "=r"(r[0]), "=r"(r[1]), "=r"(r[2]), "=r"(r[3]) : "r"(addr));
}
__device__ __forceinline__ void mma16816(float* c, const uint32_t* a, const uint32_t* b) {
    asm volatile("mma.sync.aligned.m16n8k16.row.col.f32.bf16.bf16.f32 "
        "{%0,%1,%2,%3}, {%4,%5,%6,%7}, {%8,%9}, {%0,%1,%2,%3};"
        : "+f"(c[0]), "+f"(c[1]), "+f"(c[2]), "+f"(c[3])
        : "r"(a[0]), "r"(a[1]), "r"(a[2]), "r"(a[3]), "r"(b[0]), "r"(b[1]));
}

// ---------------------------------------------------------------------------
// CSR build
// ---------------------------------------------------------------------------
__global__ void k_zero_int(int* p, int n) {
    int i = blockIdx.x * blockDim.x + threadIdx.x;
    if (i < n) p[i] = 0;
}

__global__ void k_hist(const int* __restrict__ ei, int E, int N, int* __restrict__ deg) {
    int e = blockIdx.x * blockDim.x + threadIdx.x;
    if (e >= E + N) return;
    int dst = (e < E) ? ei[E + e] : (e - E);
    atomicAdd(&deg[dst], 1);
}

__global__ void k_scan1(const int* __restrict__ deg, int* __restrict__ rowptr,
                        int* __restrict__ bsums, int n) {
    __shared__ int sh[SCAN_B];
    int i = blockIdx.x * SCAN_B + threadIdx.x;
    int v = (i < n) ? deg[i] : 0;
    sh[threadIdx.x] = v;
    __syncthreads();
    for (int off = 1; off < SCAN_B; off <<= 1) {
        int t = 0;
        if ((int)threadIdx.x >= off) t = sh[threadIdx.x - off];
        __syncthreads();
        sh[threadIdx.x] += t;
        __syncthreads();
    }
    if (i < n) rowptr[i] = sh[threadIdx.x] - v;
    if (threadIdx.x == SCAN_B - 1) bsums[blockIdx.x] = sh[SCAN_B - 1];
}

__global__ void k_scan2(int* bsums, int nb) {
    if (threadIdx.x == 0) {
        int run = 0;
        for (int i = 0; i < nb; i++) { int v = bsums[i]; bsums[i] = run; run += v; }
    }
}

__global__ void k_scan3(int* __restrict__ rowptr, const int* __restrict__ bsums,
                        int n, int etot, int* __restrict__ cursor) {
    int i = blockIdx.x * blockDim.x + threadIdx.x;
    if (i < n) {
        int v = rowptr[i] + bsums[i / SCAN_B];
        rowptr[i] = v;
        cursor[i] = v;
    }
    if (i == 0) rowptr[n] = etot;
}

__global__ void k_scatter(const int* __restrict__ ei, int E, int N,
                          int* __restrict__ cursor, int* __restrict__ srcs) {
    int e = blockIdx.x * blockDim.x + threadIdx.x;
    if (e >= E + N) return;
    int src, dst;
    if (e < E) { src = ei[e]; dst = ei[E + e]; }
    else       { src = dst = e - E; }
    int p = atomicAdd(&cursor[dst], 1);
    srcs[p] = src;
}

// ---------------------------------------------------------------------------
// fp32 -> (bf16 hi, bf16 lo) split
// ---------------------------------------------------------------------------
__global__ void k_split(const float* __restrict__ x, __nv_bfloat16* __restrict__ hi,
                        __nv_bfloat16* __restrict__ lo, int n) {
    int i = (blockIdx.x * blockDim.x + threadIdx.x) * 4;
    if (i >= n) return;
    float4 v = *(const float4*)(x + i);
    __nv_bfloat16 h0 = __float2bfloat16(v.x), h1 = __float2bfloat16(v.y);
    __nv_bfloat16 h2 = __float2bfloat16(v.z), h3 = __float2bfloat16(v.w);
    __nv_bfloat16 l0 = __float2bfloat16(v.x - __bfloat162float(h0));
    __nv_bfloat16 l1 = __float2bfloat16(v.y - __bfloat162float(h1));
    __nv_bfloat16 l2 = __float2bfloat16(v.z - __bfloat162float(h2));
    __nv_bfloat16 l3 = __float2bfloat16(v.w - __bfloat162float(h3));
    __nv_bfloat162* ph = (__nv_bfloat162*)(hi + i);
    __nv_bfloat162* pl = (__nv_bfloat162*)(lo + i);
    ph[0] = __nv_bfloat162(h0, h1); ph[1] = __nv_bfloat162(h2, h3);
    pl[0] = __nv_bfloat162(l0, l1); pl[1] = __nv_bfloat162(l2, l3);
}

// ---------------------------------------------------------------------------
// split-bf16 HMMA GEMM: C[M,Nn] = A[M,K] @ B[K,Nn]
// Tile 128x128x32, 256 threads (2x4 warps), warp tile 64x32, cp.async x2.
// C = Ahi*Bhi + Ahi*Blo + Alo*Bhi (fp32 acc).
// ---------------------------------------------------------------------------
#define STAGE_BYTES 37888
#define OFF_ALO 10240
#define OFF_BHI 20480
#define OFF_BLO 29184
#define MMA_SMEM (2 * STAGE_BYTES)

__global__ void __launch_bounds__(256) k_mma_gemm(
    const __nv_bfloat16* __restrict__ Ahi, const __nv_bfloat16* __restrict__ Alo,
    const __nv_bfloat16* __restrict__ Bhi, const __nv_bfloat16* __restrict__ Blo,
    float* __restrict__ C, int M, int K, int Nn) {
    extern __shared__ char smem[];
    uint32_t sbu = smem_to_u32(smem);
    int tid = threadIdx.x, lane = tid & 31, wid = tid >> 5;
    int wm = wid & 1, wn = wid >> 1;
    int row0 = blockIdx.y * 128, col0 = blockIdx.x * 128;

    float c[4][4][4];
#pragma unroll
    for (int i = 0; i < 4; i++)
#pragma unroll
        for (int j = 0; j < 4; j++) {
            c[i][j][0] = 0.f; c[i][j][1] = 0.f; c[i][j][2] = 0.f; c[i][j][3] = 0.f;
        }

    int nch = K >> 5;

    auto issue = [&](int ch) {
        int st = ch & 1;
        uint32_t sb = sbu + st * STAGE_BYTES;
        int k0 = ch << 5;
#pragma unroll
        for (int i = 0; i < 2; i++) {
            int g = tid + i * 256;
            int r = g >> 2, c8 = (g & 3) << 3;
            int row = row0 + r;
            if (row >= M) row = M - 1;
            size_t ga = (size_t)row * K + k0 + c8;
            uint32_t sa = sb + r * 80 + (c8 << 1);
            cp16(sa, Ahi + ga);
            cp16(sa + OFF_ALO, Alo + ga);
            int rb = g >> 4, cb = (g & 15) << 3;
            size_t gb = (size_t)(k0 + rb) * Nn + col0 + cb;
            uint32_t sB = sb + OFF_BHI + rb * 272 + (cb << 1);
            cp16(sB, Bhi + gb);
            cp16(sB + (OFF_BLO - OFF_BHI), Blo + gb);
        }
        asm volatile("cp.async.commit_group;" ::: "memory");
    };

    issue(0);
    for (int ch = 0; ch < nch; ch++) {
        if (ch + 1 < nch) {
            issue(ch + 1);
            asm volatile("cp.async.wait_group 1;" ::: "memory");
        } else {
            asm volatile("cp.async.wait_group 0;" ::: "memory");
        }
        __syncthreads();

        uint32_t sb = sbu + (ch & 1) * STAGE_BYTES;
#pragma unroll
        for (int kk2 = 0; kk2 < 2; kk2++) {
            int kk = kk2 << 4;
            uint32_t ah[4][4], al[4][4], bh[2][4], bl[2][4];
#pragma unroll
            for (int mt = 0; mt < 4; mt++) {
                uint32_t aoff = sb + (uint32_t)(wm * 64 + mt * 16 + (lane & 15)) * 80
                              + ((kk + ((lane >> 4) << 3)) << 1);
                ldsm_x4(ah[mt], aoff);
                ldsm_x4(al[mt], aoff + OFF_ALO);
            }
#pragma unroll
            for (int nt2 = 0; nt2 < 2; nt2++) {
                uint32_t boff = sb + OFF_BHI + (uint32_t)(kk + (lane & 15)) * 272
                              + ((wn * 32 + nt2 * 16 + ((lane >> 4) << 3)) << 1);
                ldsm_x4_t(bh[nt2], boff);
                ldsm_x4_t(bl[nt2], boff + (OFF_BLO - OFF_BHI));
            }
#pragma unroll
            for (int mt = 0; mt < 4; mt++)
#pragma unroll
                for (int nt = 0; nt < 4; nt++) {
                    const uint32_t* bhp = &bh[nt >> 1][(nt & 1) << 1];
                    const uint32_t* blp = &bl[nt >> 1][(nt & 1) << 1];
                    mma16816(c[mt][nt], ah[mt], bhp);
                    mma16816(c[mt][nt], ah[mt], blp);
                    mma16816(c[mt][nt], al[mt], bhp);
                }
        }
        __syncthreads();
    }

#pragma unroll
    for (int mt = 0; mt < 4; mt++) {
        int r = row0 + wm * 64 + mt * 16 + (lane >> 2);
#pragma unroll
        for (int nt = 0; nt < 4; nt++) {
            int col = col0 + wn * 32 + nt * 8 + ((lane & 3) << 1);
            if (r < M) {
                float2 v = make_float2(c[mt][nt][0], c[mt][nt][1]);
                *(float2*)(C + (size_t)r * Nn + col) = v;
            }
            if (r + 8 < M) {
                float2 v = make_float2(c[mt][nt][2], c[mt][nt][3]);
                *(float2*)(C + (size_t)(r + 8) * Nn + col) = v;
            }
        }
    }
}

// ---------------------------------------------------------------------------
// fp32 SIMT SGEMM (layer 4 only)
// ---------------------------------------------------------------------------
__global__ void k_sgemm(const float* __restrict__ A, const float* __restrict__ B,
                        float* __restrict__ C, int M, int K, int Nn) {
    __shared__ float As[16][68];
    __shared__ float Bs[16][68];
    int tid = threadIdx.x;
    int tx = tid & 15;
    int ty = tid >> 4;
    int row0 = blockIdx.y * 64;
    int col0 = blockIdx.x * 64;

    int arow = tid >> 2;
    int acol = (tid & 3) * 4;
    int brow = tid >> 4;
    int bcol = (tid & 15) * 4;

    float acc[4][4];
#pragma unroll
    for (int i = 0; i < 4; i++)
#pragma unroll
        for (int j = 0; j < 4; j++) acc[i][j] = 0.f;

    for (int k0 = 0; k0 < K; k0 += 16) {
        float4 av = make_float4(0.f, 0.f, 0.f, 0.f);
        if (row0 + arow < M)
            av = *(const float4*)(A + (size_t)(row0 + arow) * K + k0 + acol);
        As[acol + 0][arow] = av.x;
        As[acol + 1][arow] = av.y;
        As[acol + 2][arow] = av.z;
        As[acol + 3][arow] = av.w;

        float4 bv = make_float4(0.f, 0.f, 0.f, 0.f);
        if (col0 + bcol < Nn)
            bv = *(const float4*)(B + (size_t)(k0 + brow) * Nn + col0 + bcol);
        Bs[brow][bcol + 0] = bv.x;
        Bs[brow][bcol + 1] = bv.y;
        Bs[brow][bcol + 2] = bv.z;
        Bs[brow][bcol + 3] = bv.w;
        __syncthreads();

#pragma unroll
        for (int kk = 0; kk < 16; kk++) {
            float4 a4 = *(const float4*)&As[kk][ty * 4];
            float4 b4 = *(const float4*)&Bs[kk][tx * 4];
            float a[4] = {a4.x, a4.y, a4.z, a4.w};
            float b[4] = {b4.x, b4.y, b4.z, b4.w};
#pragma unroll
            for (int i = 0; i < 4; i++)
#pragma unroll
                for (int j = 0; j < 4; j++) acc[i][j] += a[i] * b[j];
        }
        __syncthreads();
    }

#pragma unroll
    for (int i = 0; i < 4; i++) {
        int r = row0 + ty * 4 + i;
        if (r >= M) break;
#pragma unroll
        for (int j = 0; j < 4; j++) {
            int cc = col0 + tx * 4 + j;
            if (cc < Nn) C[(size_t)r * Nn + cc] = acc[i][j];
        }
    }
}

// ---------------------------------------------------------------------------
// Attention coefficients
// ---------------------------------------------------------------------------
__global__ void k_attcoef(const float* __restrict__ h, const float* __restrict__ as,
                          const float* __restrict__ ad, float* __restrict__ out_s,
                          float* __restrict__ out_d, int N, int H, int C) {
    int wid = blockIdx.x * (blockDim.x >> 5) + (threadIdx.x >> 5);
    int lane = threadIdx.x & 31;
    if (wid >= N * H) return;
    int n = wid / H;
    int hh = wid - n * H;
    int F = H * C;
    const float* hr = h + (size_t)n * F + hh * C;
    const float* asr = as + hh * C;
    const float* adr = ad + hh * C;
    float s = 0.f, d = 0.f;
    for (int c = lane; c < C; c += 32) {
        float v = hr[c];
        s += v * asr[c];
        d += v * adr[c];
    }
#pragma unroll
    for (int o = 16; o; o >>= 1) {
        s += __shfl_xor_sync(0xffffffffu, s, o);
        d += __shfl_xor_sync(0xffffffffu, d, o);
    }
    if (lane == 0) {
        out_s[wid] = s;
        out_d[wid] = d;
    }
}

// ---------------------------------------------------------------------------
// Per-node segment softmax. w head-major [H][Etot].
// Pass 1: gather + leaky-relu, store logits (coalesced), track max.
// Pass 2: linear re-read, exp, store weight, sum.
// ---------------------------------------------------------------------------
__global__ void k_attn(const float* __restrict__ a_s, const float* __restrict__ a_d,
                       const int* __restrict__ rowptr, const int* __restrict__ srcs,
                       float* __restrict__ w, float* __restrict__ invs, int H, int Etot) {
    int n = blockIdx.x;
    int hh = threadIdx.x >> 5;
    int lane = threadIdx.x & 31;
    int st = rowptr[n], en = rowptr[n + 1];
    float adv = a_d[n * H + hh];
    float* wh = w + (size_t)hh * Etot;

    float mx = -1e30f;
    for (int i = st + lane; i < en; i += 32) {
        float v = a_s[srcs[i] * H + hh] + adv;
        v = v >= 0.f ? v : 0.2f * v;
        wh[i] = v;
        mx = fmaxf(mx, v);
    }
#pragma unroll
    for (int o = 16; o; o >>= 1) mx = fmaxf(mx, __shfl_xor_sync(0xffffffffu, mx, o));

    float sum = 0.f;
    for (int i = st + lane; i < en; i += 32) {
        float ex = __expf(wh[i] - mx);
        wh[i] = ex;
        sum += ex;
    }
#pragma unroll
    for (int o = 16; o; o >>= 1) sum += __shfl_xor_sync(0xffffffffu, sum, o);
    if (lane == 0) invs[n * H + hh] = 1.f / sum;
}

// ---------------------------------------------------------------------------
// Aggregation: block per node, float4 per thread, edge loop unrolled x4.
// out[n,f] = (sum_e h[src_e,f] * w[head,e]) * invs[n,head] + bias[f]
// ---------------------------------------------------------------------------
__global__ void k_agg(const float* __restrict__ h, const float* __restrict__ w,
                      const float* __restrict__ invs, const int* __restrict__ rowptr,
                      const int* __restrict__ srcs, const float* __restrict__ bias,
                      float* __restrict__ out, int H, int C, int F, int Etot) {
    int n = blockIdx.x;
    int f4 = threadIdx.x << 2;
    if (f4 >= F) return;
    int hh = f4 / C;
    const float* wh = w + (size_t)hh * Etot;
    int st = rowptr[n], en = rowptr[n + 1];
    float ci = invs[n * H + hh];
    float ax = 0.f, ay = 0.f, az = 0.f, aw = 0.f;

    int e = st;
    for (; e + 4 <= en; e += 4) {
        int s0 = srcs[e], s1 = srcs[e + 1], s2 = srcs[e + 2], s3 = srcs[e + 3];
        float a0 = wh[e], a1 = wh[e + 1], a2 = wh[e + 2], a3 = wh[e + 3];
        float4 v0 = *(const float4*)(h + (size_t)s0 * F + f4);
        float4 v1 = *(const float4*)(h + (size_t)s1 * F + f4);
        float4 v2 = *(const float4*)(h + (size_t)s2 * F + f4);
        float4 v3 = *(const float4*)(h + (size_t)s3 * F + f4);
        ax += v0.x * a0 + v1.x * a1 + v2.x * a2 + v3.x * a3;
        ay += v0.y * a0 + v1.y * a1 + v2.y * a2 + v3.y * a3;
        az += v0.z * a0 + v1.z * a1 + v2.z * a2 + v3.z * a3;
        aw += v0.w * a0 + v1.w * a1 + v2.w * a2 + v3.w * a3;
    }
    for (; e < en; e++) {
        int s = srcs[e];
        float a = wh[e];
        float4 v = *(const float4*)(h + (size_t)s * F + f4);
        ax += v.x * a; ay += v.y * a; az += v.z * a; aw += v.w * a;
    }
    float4 b = *(const float4*)(bias + f4);
    float4 o;
    o.x = ax * ci + b.x;
    o.y = ay * ci + b.y;
    o.z = az * ci + b.z;
    o.w = aw * ci + b.w;
    *(float4*)(out + (size_t)n * F + f4) = o;
}

// ---------------------------------------------------------------------------
// BatchNorm + ELU (fused with bf16 hi/lo split of the output)
// ---------------------------------------------------------------------------
__global__ void k_zero_f2(float* a, float* b, int n) {
    int i = blockIdx.x * blockDim.x + threadIdx.x;
    if (i < n) { a[i] = 0.f; b[i] = 0.f; }
}

__global__ void k_bnstats(const float* __restrict__ x, float* __restrict__ csum,
                          float* __restrict__ csq, int N, int F) {
    int c = threadIdx.x;
    float s = 0.f, sq = 0.f;
    for (int r = blockIdx.x; r < N; r += gridDim.x) {
        float v = x[(size_t)r * F + c];
        s += v;
        sq += v * v;
    }
    atomicAdd(&csum[c], s);
    atomicAdd(&csq[c], sq);
}

__global__ void k_bnapply_split(const float* __restrict__ in, float* __restrict__ out,
                                __nv_bfloat16* __restrict__ hi, __nv_bfloat16* __restrict__ lo,
                                const float* __restrict__ csum, const float* __restrict__ csq,
                                const float* __restrict__ gamma, const float* __restrict__ beta,
                                int N, int F) {
    int idx = blockIdx.x * blockDim.x + threadIdx.x;
    if (idx >= N * F) return;
    int c = idx % F;
    float invN = 1.f / (float)N;
    float mean = csum[c] * invN;
    float var = csq[c] * invN - mean * mean;
    float v = (in[idx] - mean) * rsqrtf(var + 1e-5f) * gamma[c] + beta[c];
    v = v > 0.f ? v : (__expf(v) - 1.f);
    out[idx] = v;
    __nv_bfloat16 h = __float2bfloat16(v);
    hi[idx] = h;
    lo[idx] = __float2bfloat16(v - __bfloat162float(h));
}

// ---------------------------------------------------------------------------
// log_softmax over 16 classes
// ---------------------------------------------------------------------------
__global__ void k_logsoftmax16(const float* __restrict__ in, float* __restrict__ out, int N) {
    int n = blockIdx.x * blockDim.x + threadIdx.x;
    if (n >= N) return;
    const float* r = in + n * 16;
    float mx = r[0];
#pragma unroll
    for (int j = 1; j < 16; j++) mx = fmaxf(mx, r[j]);
    float s = 0.f;
#pragma unroll
    for (int j = 0; j < 16; j++) s += __expf(r[j] - mx);
    float ls = logf(s) + mx;
    float* o = out + n * 16;
#pragma unroll
    for (int j = 0; j < 16; j++) o[j] = r[j] - ls;
}

// ---------------------------------------------------------------------------
// Host orchestration
// ---------------------------------------------------------------------------
extern "C" void kernel_launch(void* const* d_in, const int* in_sizes, int n_in,
                              void* d_out, int out_size) {
    const float* x = (const float*)d_in[0];
    const int* ei = (const int*)d_in[1];
    int N = in_sizes[0] / 512;
    int E = in_sizes[1] / 2;
    int Etot = E + N;

    float *p_h, *p_y, *p_agg, *p_as, *p_ad, *p_w, *p_invs, *p_csum, *p_csq;
    int *p_deg, *p_rowptr, *p_cursor, *p_srcs, *p_bsums;
    __nv_bfloat16 *p_ahi, *p_alo, *p_bhi, *p_blo;
    cudaGetSymbolAddress((void**)&p_h, g_h);
    cudaGetSymbolAddress((void**)&p_y, g_y);
    cudaGetSymbolAddress((void**)&p_agg, g_agg);
    cudaGetSymbolAddress((void**)&p_as, g_as);
    cudaGetSymbolAddress((void**)&p_ad, g_ad);
    cudaGetSymbolAddress((void**)&p_w, g_w);
    cudaGetSymbolAddress((void**)&p_invs, g_invs);
    cudaGetSymbolAddress((void**)&p_csum, g_colsum);
    cudaGetSymbolAddress((void**)&p_csq, g_colsq);
    cudaGetSymbolAddress((void**)&p_deg, g_deg);
    cudaGetSymbolAddress((void**)&p_rowptr, g_rowptr);
    cudaGetSymbolAddress((void**)&p_cursor, g_cursor);
    cudaGetSymbolAddress((void**)&p_srcs, g_srcs);
    cudaGetSymbolAddress((void**)&p_bsums, g_bsums);
    cudaGetSymbolAddress((void**)&p_ahi, g_ahi);
    cudaGetSymbolAddress((void**)&p_alo, g_alo);
    cudaGetSymbolAddress((void**)&p_bhi, g_bhi);
    cudaGetSymbolAddress((void**)&p_blo, g_blo);

    cudaFuncSetAttribute(k_mma_gemm, cudaFuncAttributeMaxDynamicSharedMemorySize, MMA_SMEM);

    struct Cfg { int Fin, H, C, iW; bool bn; };
    const Cfg cfgs[4] = {
        {512, 8, 64, 2, true},
        {512, 4, 64, 8, true},
        {256, 2, 64, 14, true},
        {128, 1, 16, 20, false},
    };

    // ---- Layer-1 GEMM first (also puts heavy kernel at launch slot 4 for ncu) ----
    {
        int nel = N * 512;
        k_zero_int<<<(N + 255) / 256, 256>>>(p_deg, N);                               // 1
        k_split<<<(nel / 4 + 255) / 256, 256>>>(x, p_ahi, p_alo, nel);                // 2
        int nw = 512 * 512;
        k_split<<<(nw / 4 + 255) / 256, 256>>>((const float*)d_in[2], p_bhi, p_blo, nw); // 3
        dim3 gg(512 / 128, (N + 127) / 128);
        k_mma_gemm<<<gg, 256, MMA_SMEM>>>(p_ahi, p_alo, p_bhi, p_blo, p_h, N, 512, 512); // 4
    }

    // ---- CSR build (independent of GEMM) ----
    k_hist<<<(Etot + 255) / 256, 256>>>(ei, E, N, p_deg);
    int nblk = (N + SCAN_B - 1) / SCAN_B;
    k_scan1<<<nblk, SCAN_B>>>(p_deg, p_rowptr, p_bsums, N);
    k_scan2<<<1, 32>>>(p_bsums, nblk);
    k_scan3<<<(N + 255) / 256, 256>>>(p_rowptr, p_bsums, N, Etot, p_cursor);
    k_scatter<<<(Etot + 255) / 256, 256>>>(ei, E, N, p_cursor, p_srcs);

    const float* in = x;
    for (int li = 0; li < 4; li++) {
        const Cfg& cf = cfgs[li];
        int F = cf.H * cf.C;
        const float* W  = (const float*)d_in[cf.iW + 0];
        const float* as = (const float*)d_in[cf.iW + 1];
        const float* ad = (const float*)d_in[cf.iW + 2];
        const float* bi = (const float*)d_in[cf.iW + 3];

        if (li >= 1 && li < 3) {
            int nw = cf.Fin * F;
            k_split<<<(nw / 4 + 255) / 256, 256>>>(W, p_bhi, p_blo, nw);
            dim3 gg(F / 128, (N + 127) / 128);
            k_mma_gemm<<<gg, 256, MMA_SMEM>>>(p_ahi, p_alo, p_bhi, p_blo, p_h, N, cf.Fin, F);
        } else if (li == 3) {
            dim3 ggrid((F + 63) / 64, (N + 63) / 64);
            k_sgemm<<<ggrid, 256>>>(in, W, p_h, N, cf.Fin, F);
        }
        // (li == 0: GEMM already issued above)

        int pairs = N * cf.H;
        k_attcoef<<<(pairs + 3) / 4, 128>>>(p_h, as, ad, p_as, p_ad, N, cf.H, cf.C);
        k_attn<<<N, 32 * cf.H>>>(p_as, p_ad, p_rowptr, p_srcs, p_w, p_invs, cf.H, Etot);
        int T = (F >= 128) ? (F >> 2) : 32;
        k_agg<<<N, T>>>(p_h, p_w, p_invs, p_rowptr, p_srcs, bi, p_agg, cf.H, cf.C, F, Etot);

        if (cf.bn) {
            const float* gamma = (const float*)d_in[cf.iW + 4];
            const float* beta  = (const float*)d_in[cf.iW + 5];
            k_zero_f2<<<1, F>>>(p_csum, p_csq, F);
            k_bnstats<<<240, F>>>(p_agg, p_csum, p_csq, N, F);
            k_bnapply_split<<<(N * F + 255) / 256, 256>>>(p_agg, p_y, p_ahi, p_alo,
                                                          p_csum, p_csq, gamma, beta, N, F);
            in = p_y;
        } else {
            k_logsoftmax16<<<(N + 255) / 256, 256>>>(p_agg, (float*)d_out, N);
        }
    }
}

// round 5
// speedup vs baseline: 1.8890x; 1.0368x over previous
#include <cuda_runtime.h>
#include <cuda_bf16.h>
#include <cstdint>
#include <math.h>

// ---------------------------------------------------------------------------
// GAT 4-layer network.
//   - CSR build (dst-sorted) once per call
//   - Layers 1-3: split-bf16 HMMA GEMM (mma.sync m16n8k16), 3-stage cp.async
//     pipeline, attention coefficients fused into the epilogue.
//   - Layer 4: exact fp32 SIMT GEMM (tiny) + separate attcoef.
//   - per-node segment softmax (head-major edge buf), per-node aggregation
//     (float4 + unroll-8), BN+ELU (+bf16 re-split), log_softmax.
// ---------------------------------------------------------------------------

#define MAXN 20000
#define MAXE 360000
#define MAXF 512
#define MAXH 8
#define SCAN_B 512

__device__ float g_h[MAXN * MAXF];
__device__ float g_y[MAXN * MAXF];
__device__ float g_agg[MAXN * MAXF];
__device__ float g_as[MAXN * MAXH];
__device__ float g_ad[MAXN * MAXH];
__device__ float g_w[MAXE * MAXH];     // head-major: [H][Etot]
__device__ float g_invs[MAXN * MAXH];
__device__ int   g_deg[MAXN];
__device__ int   g_rowptr[MAXN + 1];
__device__ int   g_cursor[MAXN];
__device__ int   g_srcs[MAXE];
__device__ float g_colsum[MAXF];
__device__ float g_colsq[MAXF];
__device__ int   g_bsums[64];
__device__ __nv_bfloat16 g_ahi[MAXN * MAXF];
__device__ __nv_bfloat16 g_alo[MAXN * MAXF];
__device__ __nv_bfloat16 g_bhi[MAXF * MAXF];
__device__ __nv_bfloat16 g_blo[MAXF * MAXF];

// ---------------------------------------------------------------------------
// PTX helpers
// ---------------------------------------------------------------------------
__device__ __forceinline__ uint32_t smem_to_u32(const void* p) {
    uint32_t a;
    asm("{ .reg .u64 t; cvta.to.shared.u64 t, %1; cvt.u32.u64 %0, t; }" : "=r"(a) : "l"(p));
    return a;
}
__device__ __forceinline__ void cp16(uint32_t s, const void* g) {
    asm volatile("cp.async.cg.shared.global [%0], [%1], 16;" :: "r"(s), "l"(g));
}
__device__ __forceinline__ void ldsm_x4(uint32_t* r, uint32_t addr) {
    asm volatile("ldmatrix.sync.aligned.m8n8.x4.shared.b16 {%0,%1,%2,%3}, [%4];"
        : "=r"(r[0]), "=r"(r[1]), "=r"(r[2]), "=r"(r[3]) : "r"(addr));
}
__device__ __forceinline__ void ldsm_x4_t(uint32_t* r, uint32_t addr) {
    asm volatile("ldmatrix.sync.aligned.m8n8.x4.trans.shared.b16 {%0,%1,%2,%3}, [%4];"
        : "=r"(r[0]), "=r"(r[1]), "=r"(r[2]), "=r"(r[3]) : "r"(addr));
}
__device__ __forceinline__ void mma16816(float* c, const uint32_t* a, const uint32_t* b) {
    asm volatile("mma.sync.aligned.m16n8k16.row.col.f32.bf16.bf16.f32 "
        "{%0,%1,%2,%3}, {%4,%5,%6,%7}, {%8,%9}, {%0,%1,%2,%3};"
        : "+f"(c[0]), "+f"(c[1]), "+f"(c[2]), "+f"(c[3])
        : "r"(a[0]), "r"(a[1]), "r"(a[2]), "r"(a[3]), "r"(b[0]), "r"(b[1]));
}

// ---------------------------------------------------------------------------
// CSR build
// ---------------------------------------------------------------------------
__global__ void k_zero_int(int* p, int n) {
    int i = blockIdx.x * blockDim.x + threadIdx.x;
    if (i < n) p[i] = 0;
}

__global__ void k_hist(const int* __restrict__ ei, int E, int N, int* __restrict__ deg) {
    int e = blockIdx.x * blockDim.x + threadIdx.x;
    if (e >= E + N) return;
    int dst = (e < E) ? ei[E + e] : (e - E);
    atomicAdd(&deg[dst], 1);
}

__global__ void k_scan1(const int* __restrict__ deg, int* __restrict__ rowptr,
                        int* __restrict__ bsums, int n) {
    __shared__ int sh[SCAN_B];
    int i = blockIdx.x * SCAN_B + threadIdx.x;
    int v = (i < n) ? deg[i] : 0;
    sh[threadIdx.x] = v;
    __syncthreads();
    for (int off = 1; off < SCAN_B; off <<= 1) {
        int t = 0;
        if ((int)threadIdx.x >= off) t = sh[threadIdx.x - off];
        __syncthreads();
        sh[threadIdx.x] += t;
        __syncthreads();
    }
    if (i < n) rowptr[i] = sh[threadIdx.x] - v;
    if (threadIdx.x == SCAN_B - 1) bsums[blockIdx.x] = sh[SCAN_B - 1];
}

__global__ void k_scan2(int* bsums, int nb) {
    if (threadIdx.x == 0) {
        int run = 0;
        for (int i = 0; i < nb; i++) { int v = bsums[i]; bsums[i] = run; run += v; }
    }
}

__global__ void k_scan3(int* __restrict__ rowptr, const int* __restrict__ bsums,
                        int n, int etot, int* __restrict__ cursor) {
    int i = blockIdx.x * blockDim.x + threadIdx.x;
    if (i < n) {
        int v = rowptr[i] + bsums[i / SCAN_B];
        rowptr[i] = v;
        cursor[i] = v;
    }
    if (i == 0) rowptr[n] = etot;
}

__global__ void k_scatter(const int* __restrict__ ei, int E, int N,
                          int* __restrict__ cursor, int* __restrict__ srcs) {
    int e = blockIdx.x * blockDim.x + threadIdx.x;
    if (e >= E + N) return;
    int src, dst;
    if (e < E) { src = ei[e]; dst = ei[E + e]; }
    else       { src = dst = e - E; }
    int p = atomicAdd(&cursor[dst], 1);
    srcs[p] = src;
}

// ---------------------------------------------------------------------------
// fp32 -> (bf16 hi, bf16 lo) split
// ---------------------------------------------------------------------------
__global__ void k_split(const float* __restrict__ x, __nv_bfloat16* __restrict__ hi,
                        __nv_bfloat16* __restrict__ lo, int n) {
    int i = (blockIdx.x * blockDim.x + threadIdx.x) * 4;
    if (i >= n) return;
    float4 v = *(const float4*)(x + i);
    __nv_bfloat16 h0 = __float2bfloat16(v.x), h1 = __float2bfloat16(v.y);
    __nv_bfloat16 h2 = __float2bfloat16(v.z), h3 = __float2bfloat16(v.w);
    __nv_bfloat16 l0 = __float2bfloat16(v.x - __bfloat162float(h0));
    __nv_bfloat16 l1 = __float2bfloat16(v.y - __bfloat162float(h1));
    __nv_bfloat16 l2 = __float2bfloat16(v.z - __bfloat162float(h2));
    __nv_bfloat16 l3 = __float2bfloat16(v.w - __bfloat162float(h3));
    __nv_bfloat162* ph = (__nv_bfloat162*)(hi + i);
    __nv_bfloat162* pl = (__nv_bfloat162*)(lo + i);
    ph[0] = __nv_bfloat162(h0, h1); ph[1] = __nv_bfloat162(h2, h3);
    pl[0] = __nv_bfloat162(l0, l1); pl[1] = __nv_bfloat162(l2, l3);
}

// ---------------------------------------------------------------------------
// split-bf16 HMMA GEMM + fused attention coefficients.
// C[M,Nn] = A[M,K] @ B[K,Nn]; out_s[n,h] = <C row, att_s head h>, same out_d.
// Tile 128x128x32, 3-stage cp.async pipeline, warp tile 64x32.
// C = Ahi*Bhi + Ahi*Blo + Alo*Bhi (fp32 acc). Heads are 64 cols (C=64).
// ---------------------------------------------------------------------------
#define STAGE_BYTES 37888
#define OFF_ALO 10240
#define OFF_BHI 20480
#define OFF_BLO 29184
#define MMA_SMEM (3 * STAGE_BYTES)

__global__ void __launch_bounds__(256, 2) k_mma_gemm(
    const __nv_bfloat16* __restrict__ Ahi, const __nv_bfloat16* __restrict__ Alo,
    const __nv_bfloat16* __restrict__ Bhi, const __nv_bfloat16* __restrict__ Blo,
    float* __restrict__ C, int M, int K, int Nn,
    const float* __restrict__ att_s, const float* __restrict__ att_d,
    float* __restrict__ out_s, float* __restrict__ out_d, int H) {
    extern __shared__ char smem[];
    uint32_t sbu = smem_to_u32(smem);
    int tid = threadIdx.x, lane = tid & 31, wid = tid >> 5;
    int wm = wid & 1, wn = wid >> 1;
    int row0 = blockIdx.y * 128, col0 = blockIdx.x * 128;

    float c[4][4][4];
#pragma unroll
    for (int i = 0; i < 4; i++)
#pragma unroll
        for (int j = 0; j < 4; j++) {
            c[i][j][0] = 0.f; c[i][j][1] = 0.f; c[i][j][2] = 0.f; c[i][j][3] = 0.f;
        }

    int nch = K >> 5;

    auto issue = [&](int ch) {
        uint32_t sb = sbu + (uint32_t)(ch % 3) * STAGE_BYTES;
        int k0 = ch << 5;
#pragma unroll
        for (int i = 0; i < 2; i++) {
            int g = tid + i * 256;
            int r = g >> 2, c8 = (g & 3) << 3;
            int row = row0 + r;
            if (row >= M) row = M - 1;
            size_t ga = (size_t)row * K + k0 + c8;
            uint32_t sa = sb + r * 80 + (c8 << 1);
            cp16(sa, Ahi + ga);
            cp16(sa + OFF_ALO, Alo + ga);
            int rb = g >> 4, cb = (g & 15) << 3;
            size_t gb = (size_t)(k0 + rb) * Nn + col0 + cb;
            uint32_t sB = sb + OFF_BHI + rb * 272 + (cb << 1);
            cp16(sB, Bhi + gb);
            cp16(sB + (OFF_BLO - OFF_BHI), Blo + gb);
        }
        asm volatile("cp.async.commit_group;" ::: "memory");
    };

    issue(0);
    issue(1);
    for (int ch = 0; ch < nch; ch++) {
        if (ch + 1 < nch)
            asm volatile("cp.async.wait_group 1;" ::: "memory");
        else
            asm volatile("cp.async.wait_group 0;" ::: "memory");
        __syncthreads();
        if (ch + 2 < nch) issue(ch + 2);

        uint32_t sb = sbu + (uint32_t)(ch % 3) * STAGE_BYTES;
#pragma unroll
        for (int kk2 = 0; kk2 < 2; kk2++) {
            int kk = kk2 << 4;
            uint32_t ah[4][4], al[4][4], bh[2][4], bl[2][4];
#pragma unroll
            for (int mt = 0; mt < 4; mt++) {
                uint32_t aoff = sb + (uint32_t)(wm * 64 + mt * 16 + (lane & 15)) * 80
                              + ((kk + ((lane >> 4) << 3)) << 1);
                ldsm_x4(ah[mt], aoff);
                ldsm_x4(al[mt], aoff + OFF_ALO);
            }
#pragma unroll
            for (int nt2 = 0; nt2 < 2; nt2++) {
                uint32_t boff = sb + OFF_BHI + (uint32_t)(kk + (lane & 15)) * 272
                              + ((wn * 32 + nt2 * 16 + ((lane >> 4) << 3)) << 1);
                ldsm_x4_t(bh[nt2], boff);
                ldsm_x4_t(bl[nt2], boff + (OFF_BLO - OFF_BHI));
            }
#pragma unroll
            for (int mt = 0; mt < 4; mt++)
#pragma unroll
                for (int nt = 0; nt < 4; nt++) {
                    const uint32_t* bhp = &bh[nt >> 1][(nt & 1) << 1];
                    const uint32_t* blp = &bl[nt >> 1][(nt & 1) << 1];
                    mma16816(c[mt][nt], ah[mt], bhp);
                    mma16816(c[mt][nt], ah[mt], blp);
                    mma16816(c[mt][nt], al[mt], bhp);
                }
        }
        // no trailing sync (3-stage: written stage was consumed >=1 barrier ago)
    }

    // ---- C store ----
#pragma unroll
    for (int mt = 0; mt < 4; mt++) {
        int r = row0 + wm * 64 + mt * 16 + (lane >> 2);
#pragma unroll
        for (int nt = 0; nt < 4; nt++) {
            int col = col0 + wn * 32 + nt * 8 + ((lane & 3) << 1);
            if (r < M) {
                float2 v = make_float2(c[mt][nt][0], c[mt][nt][1]);
                *(float2*)(C + (size_t)r * Nn + col) = v;
            }
            if (r + 8 < M) {
                float2 v = make_float2(c[mt][nt][2], c[mt][nt][3]);
                *(float2*)(C + (size_t)(r + 8) * Nn + col) = v;
            }
        }
    }

    // ---- fused attention coefficients ----
    // Each warp's 32 cols lie within one head (C=64): head_local = wn>>1.
    __syncthreads();  // done with pipeline smem; reuse for reductions
    float* sred = (float*)smem;          // [2][128]
    float* dred = sred + 256;            // [2][128]
    sred[tid] = 0.f;
    dred[tid] = 0.f;
    __syncthreads();

    float asv[4][2], adv[4][2];
#pragma unroll
    for (int nt = 0; nt < 4; nt++) {
        int col = col0 + wn * 32 + nt * 8 + ((lane & 3) << 1);
        asv[nt][0] = att_s[col];     asv[nt][1] = att_s[col + 1];
        adv[nt][0] = att_d[col];     adv[nt][1] = att_d[col + 1];
    }
#pragma unroll
    for (int mt = 0; mt < 4; mt++) {
        float s0 = 0.f, s1 = 0.f, d0 = 0.f, d1 = 0.f;  // rows r, r+8
#pragma unroll
        for (int nt = 0; nt < 4; nt++) {
            s0 += c[mt][nt][0] * asv[nt][0] + c[mt][nt][1] * asv[nt][1];
            s1 += c[mt][nt][2] * asv[nt][0] + c[mt][nt][3] * asv[nt][1];
            d0 += c[mt][nt][0] * adv[nt][0] + c[mt][nt][1] * adv[nt][1];
            d1 += c[mt][nt][2] * adv[nt][0] + c[mt][nt][3] * adv[nt][1];
        }
#pragma unroll
        for (int o = 1; o <= 2; o <<= 1) {
            s0 += __shfl_xor_sync(0xffffffffu, s0, o);
            s1 += __shfl_xor_sync(0xffffffffu, s1, o);
            d0 += __shfl_xor_sync(0xffffffffu, d0, o);
            d1 += __shfl_xor_sync(0xffffffffu, d1, o);
        }
        if ((lane & 3) == 0) {
            int hh = wn >> 1;
            int rloc = wm * 64 + mt * 16 + (lane >> 2);
            atomicAdd(&sred[hh * 128 + rloc], s0);
            atomicAdd(&sred[hh * 128 + rloc + 8], s1);
            atomicAdd(&dred[hh * 128 + rloc], d0);
            atomicAdd(&dred[hh * 128 + rloc + 8], d1);
        }
    }
    __syncthreads();
    {
        int hh = tid >> 7;          // 0..1
        int rloc = tid & 127;       // 0..127
        int row = row0 + rloc;
        if (row < M) {
            int hglob = (col0 >> 6) + hh;
            out_s[row * H + hglob] = sred[hh * 128 + rloc];
            out_d[row * H + hglob] = dred[hh * 128 + rloc];
        }
    }
}

// ---------------------------------------------------------------------------
// fp32 SIMT SGEMM (layer 4 only)
// ---------------------------------------------------------------------------
__global__ void k_sgemm(const float* __restrict__ A, const float* __restrict__ B,
                        float* __restrict__ C, int M, int K, int Nn) {
    __shared__ float As[16][68];
    __shared__ float Bs[16][68];
    int tid = threadIdx.x;
    int tx = tid & 15;
    int ty = tid >> 4;
    int row0 = blockIdx.y * 64;
    int col0 = blockIdx.x * 64;

    int arow = tid >> 2;
    int acol = (tid & 3) * 4;
    int brow = tid >> 4;
    int bcol = (tid & 15) * 4;

    float acc[4][4];
#pragma unroll
    for (int i = 0; i < 4; i++)
#pragma unroll
        for (int j = 0; j < 4; j++) acc[i][j] = 0.f;

    for (int k0 = 0; k0 < K; k0 += 16) {
        float4 av = make_float4(0.f, 0.f, 0.f, 0.f);
        if (row0 + arow < M)
            av = *(const float4*)(A + (size_t)(row0 + arow) * K + k0 + acol);
        As[acol + 0][arow] = av.x;
        As[acol + 1][arow] = av.y;
        As[acol + 2][arow] = av.z;
        As[acol + 3][arow] = av.w;

        float4 bv = make_float4(0.f, 0.f, 0.f, 0.f);
        if (col0 + bcol < Nn)
            bv = *(const float4*)(B + (size_t)(k0 + brow) * Nn + col0 + bcol);
        Bs[brow][bcol + 0] = bv.x;
        Bs[brow][bcol + 1] = bv.y;
        Bs[brow][bcol + 2] = bv.z;
        Bs[brow][bcol + 3] = bv.w;
        __syncthreads();

#pragma unroll
        for (int kk = 0; kk < 16; kk++) {
            float4 a4 = *(const float4*)&As[kk][ty * 4];
            float4 b4 = *(const float4*)&Bs[kk][tx * 4];
            float a[4] = {a4.x, a4.y, a4.z, a4.w};
            float b[4] = {b4.x, b4.y, b4.z, b4.w};
#pragma unroll
            for (int i = 0; i < 4; i++)
#pragma unroll
                for (int j = 0; j < 4; j++) acc[i][j] += a[i] * b[j];
        }
        __syncthreads();
    }

#pragma unroll
    for (int i = 0; i < 4; i++) {
        int r = row0 + ty * 4 + i;
        if (r >= M) break;
#pragma unroll
        for (int j = 0; j < 4; j++) {
            int cc = col0 + tx * 4 + j;
            if (cc < Nn) C[(size_t)r * Nn + cc] = acc[i][j];
        }
    }
}

// ---------------------------------------------------------------------------
// Attention coefficients (layer 4 only)
// ---------------------------------------------------------------------------
__global__ void k_attcoef(const float* __restrict__ h, const float* __restrict__ as,
                          const float* __restrict__ ad, float* __restrict__ out_s,
                          float* __restrict__ out_d, int N, int H, int C) {
    int wid = blockIdx.x * (blockDim.x >> 5) + (threadIdx.x >> 5);
    int lane = threadIdx.x & 31;
    if (wid >= N * H) return;
    int n = wid / H;
    int hh = wid - n * H;
    int F = H * C;
    const float* hr = h + (size_t)n * F + hh * C;
    const float* asr = as + hh * C;
    const float* adr = ad + hh * C;
    float s = 0.f, d = 0.f;
    for (int c = lane; c < C; c += 32) {
        float v = hr[c];
        s += v * asr[c];
        d += v * adr[c];
    }
#pragma unroll
    for (int o = 16; o; o >>= 1) {
        s += __shfl_xor_sync(0xffffffffu, s, o);
        d += __shfl_xor_sync(0xffffffffu, d, o);
    }
    if (lane == 0) {
        out_s[wid] = s;
        out_d[wid] = d;
    }
}

// ---------------------------------------------------------------------------
// Per-node segment softmax. w head-major [H][Etot].
// ---------------------------------------------------------------------------
__global__ void k_attn(const float* __restrict__ a_s, const float* __restrict__ a_d,
                       const int* __restrict__ rowptr, const int* __restrict__ srcs,
                       float* __restrict__ w, float* __restrict__ invs, int H, int Etot) {
    int n = blockIdx.x;
    int hh = threadIdx.x >> 5;
    int lane = threadIdx.x & 31;
    int st = rowptr[n], en = rowptr[n + 1];
    float adv = a_d[n * H + hh];
    float* wh = w + (size_t)hh * Etot;

    float mx = -1e30f;
    for (int i = st + lane; i < en; i += 32) {
        float v = a_s[srcs[i] * H + hh] + adv;
        v = v >= 0.f ? v : 0.2f * v;
        wh[i] = v;
        mx = fmaxf(mx, v);
    }
#pragma unroll
    for (int o = 16; o; o >>= 1) mx = fmaxf(mx, __shfl_xor_sync(0xffffffffu, mx, o));

    float sum = 0.f;
    for (int i = st + lane; i < en; i += 32) {
        float ex = __expf(wh[i] - mx);
        wh[i] = ex;
        sum += ex;
    }
#pragma unroll
    for (int o = 16; o; o >>= 1) sum += __shfl_xor_sync(0xffffffffu, sum, o);
    if (lane == 0) invs[n * H + hh] = 1.f / sum;
}

// ---------------------------------------------------------------------------
// Aggregation: block per node, float4 per thread, edge loop unrolled x8.
// ---------------------------------------------------------------------------
__global__ void k_agg(const float* __restrict__ h, const float* __restrict__ w,
                      const float* __restrict__ invs, const int* __restrict__ rowptr,
                      const int* __restrict__ srcs, const float* __restrict__ bias,
                      float* __restrict__ out, int H, int C, int F, int Etot) {
    int n = blockIdx.x;
    int f4 = threadIdx.x << 2;
    if (f4 >= F) return;
    int hh = f4 / C;
    const float* wh = w + (size_t)hh * Etot;
    int st = rowptr[n], en = rowptr[n + 1];
    float ci = invs[n * H + hh];
    float ax = 0.f, ay = 0.f, az = 0.f, aw = 0.f;

    int e = st;
    for (; e + 8 <= en; e += 8) {
        int s[8];
        float a[8];
#pragma unroll
        for (int j = 0; j < 8; j++) { s[j] = srcs[e + j]; a[j] = wh[e + j]; }
        float4 v[8];
#pragma unroll
        for (int j = 0; j < 8; j++) v[j] = *(const float4*)(h + (size_t)s[j] * F + f4);
#pragma unroll
        for (int j = 0; j < 8; j++) {
            ax += v[j].x * a[j];
            ay += v[j].y * a[j];
            az += v[j].z * a[j];
            aw += v[j].w * a[j];
        }
    }
    for (; e < en; e++) {
        int s = srcs[e];
        float a = wh[e];
        float4 v = *(const float4*)(h + (size_t)s * F + f4);
        ax += v.x * a; ay += v.y * a; az += v.z * a; aw += v.w * a;
    }
    float4 b = *(const float4*)(bias + f4);
    float4 o;
    o.x = ax * ci + b.x;
    o.y = ay * ci + b.y;
    o.z = az * ci + b.z;
    o.w = aw * ci + b.w;
    *(float4*)(out + (size_t)n * F + f4) = o;
}

// ---------------------------------------------------------------------------
// BatchNorm + ELU (fused with bf16 hi/lo split of the output)
// ---------------------------------------------------------------------------
__global__ void k_zero_f2(float* a, float* b, int n) {
    int i = blockIdx.x * blockDim.x + threadIdx.x;
    if (i < n) { a[i] = 0.f; b[i] = 0.f; }
}

__global__ void k_bnstats(const float* __restrict__ x, float* __restrict__ csum,
                          float* __restrict__ csq, int N, int F) {
    int c = threadIdx.x;
    float s = 0.f, sq = 0.f;
    for (int r = blockIdx.x; r < N; r += gridDim.x) {
        float v = x[(size_t)r * F + c];
        s += v;
        sq += v * v;
    }
    atomicAdd(&csum[c], s);
    atomicAdd(&csq[c], sq);
}

__global__ void k_bnapply_split(const float* __restrict__ in, float* __restrict__ out,
                                __nv_bfloat16* __restrict__ hi, __nv_bfloat16* __restrict__ lo,
                                const float* __restrict__ csum, const float* __restrict__ csq,
                                const float* __restrict__ gamma, const float* __restrict__ beta,
                                int N, int F) {
    int idx = blockIdx.x * blockDim.x + threadIdx.x;
    if (idx >= N * F) return;
    int c = idx % F;
    float invN = 1.f / (float)N;
    float mean = csum[c] * invN;
    float var = csq[c] * invN - mean * mean;
    float v = (in[idx] - mean) * rsqrtf(var + 1e-5f) * gamma[c] + beta[c];
    v = v > 0.f ? v : (__expf(v) - 1.f);
    out[idx] = v;
    __nv_bfloat16 h = __float2bfloat16(v);
    hi[idx] = h;
    lo[idx] = __float2bfloat16(v - __bfloat162float(h));
}

// ---------------------------------------------------------------------------
// log_softmax over 16 classes
// ---------------------------------------------------------------------------
__global__ void k_logsoftmax16(const float* __restrict__ in, float* __restrict__ out, int N) {
    int n = blockIdx.x * blockDim.x + threadIdx.x;
    if (n >= N) return;
    const float* r = in + n * 16;
    float mx = r[0];
#pragma unroll
    for (int j = 1; j < 16; j++) mx = fmaxf(mx, r[j]);
    float s = 0.f;
#pragma unroll
    for (int j = 0; j < 16; j++) s += __expf(r[j] - mx);
    float ls = logf(s) + mx;
    float* o = out + n * 16;
#pragma unroll
    for (int j = 0; j < 16; j++) o[j] = r[j] - ls;
}

// ---------------------------------------------------------------------------
// Host orchestration
// ---------------------------------------------------------------------------
extern "C" void kernel_launch(void* const* d_in, const int* in_sizes, int n_in,
                              void* d_out, int out_size) {
    const float* x = (const float*)d_in[0];
    const int* ei = (const int*)d_in[1];
    int N = in_sizes[0] / 512;
    int E = in_sizes[1] / 2;
    int Etot = E + N;

    float *p_h, *p_y, *p_agg, *p_as, *p_ad, *p_w, *p_invs, *p_csum, *p_csq;
    int *p_deg, *p_rowptr, *p_cursor, *p_srcs, *p_bsums;
    __nv_bfloat16 *p_ahi, *p_alo, *p_bhi, *p_blo;
    cudaGetSymbolAddress((void**)&p_h, g_h);
    cudaGetSymbolAddress((void**)&p_y, g_y);
    cudaGetSymbolAddress((void**)&p_agg, g_agg);
    cudaGetSymbolAddress((void**)&p_as, g_as);
    cudaGetSymbolAddress((void**)&p_ad, g_ad);
    cudaGetSymbolAddress((void**)&p_w, g_w);
    cudaGetSymbolAddress((void**)&p_invs, g_invs);
    cudaGetSymbolAddress((void**)&p_csum, g_colsum);
    cudaGetSymbolAddress((void**)&p_csq, g_colsq);
    cudaGetSymbolAddress((void**)&p_deg, g_deg);
    cudaGetSymbolAddress((void**)&p_rowptr, g_rowptr);
    cudaGetSymbolAddress((void**)&p_cursor, g_cursor);
    cudaGetSymbolAddress((void**)&p_srcs, g_srcs);
    cudaGetSymbolAddress((void**)&p_bsums, g_bsums);
    cudaGetSymbolAddress((void**)&p_ahi, g_ahi);
    cudaGetSymbolAddress((void**)&p_alo, g_alo);
    cudaGetSymbolAddress((void**)&p_bhi, g_bhi);
    cudaGetSymbolAddress((void**)&p_blo, g_blo);

    cudaFuncSetAttribute(k_mma_gemm, cudaFuncAttributeMaxDynamicSharedMemorySize, MMA_SMEM);

    struct Cfg { int Fin, H, C, iW; bool bn; };
    const Cfg cfgs[4] = {
        {512, 8, 64, 2, true},
        {512, 4, 64, 8, true},
        {256, 2, 64, 14, true},
        {128, 1, 16, 20, false},
    };

    // ---- Layer-1 prep + GEMM ----
    {
        int nel = N * 512;
        k_zero_int<<<(N + 255) / 256, 256>>>(p_deg, N);
        k_split<<<(nel / 4 + 255) / 256, 256>>>(x, p_ahi, p_alo, nel);
        int nw = 512 * 512;
        k_split<<<(nw / 4 + 255) / 256, 256>>>((const float*)d_in[2], p_bhi, p_blo, nw);
        dim3 gg(512 / 128, (N + 127) / 128);
        k_mma_gemm<<<gg, 256, MMA_SMEM>>>(p_ahi, p_alo, p_bhi, p_blo, p_h, N, 512, 512,
                                          (const float*)d_in[3], (const float*)d_in[4],
                                          p_as, p_ad, 8);
    }

    // ---- CSR build ----
    k_hist<<<(Etot + 255) / 256, 256>>>(ei, E, N, p_deg);
    int nblk = (N + SCAN_B - 1) / SCAN_B;
    k_scan1<<<nblk, SCAN_B>>>(p_deg, p_rowptr, p_bsums, N);
    k_scan2<<<1, 32>>>(p_bsums, nblk);
    k_scan3<<<(N + 255) / 256, 256>>>(p_rowptr, p_bsums, N, Etot, p_cursor);
    k_scatter<<<(Etot + 255) / 256, 256>>>(ei, E, N, p_cursor, p_srcs);

    const float* in = x;
    for (int li = 0; li < 4; li++) {
        const Cfg& cf = cfgs[li];
        int F = cf.H * cf.C;
        const float* W  = (const float*)d_in[cf.iW + 0];
        const float* as = (const float*)d_in[cf.iW + 1];
        const float* ad = (const float*)d_in[cf.iW + 2];
        const float* bi = (const float*)d_in[cf.iW + 3];

        if (li >= 1 && li < 3) {
            int nw = cf.Fin * F;
            k_split<<<(nw / 4 + 255) / 256, 256>>>(W, p_bhi, p_blo, nw);
            dim3 gg(F / 128, (N + 127) / 128);
            k_mma_gemm<<<gg, 256, MMA_SMEM>>>(p_ahi, p_alo, p_bhi, p_blo, p_h, N, cf.Fin, F,
                                              as, ad, p_as, p_ad, cf.H);
        } else if (li == 3) {
            dim3 ggrid((F + 63) / 64, (N + 63) / 64);
            k_sgemm<<<ggrid, 256>>>(in, W, p_h, N, cf.Fin, F);
            int pairs = N * cf.H;
            k_attcoef<<<(pairs + 3) / 4, 128>>>(p_h, as, ad, p_as, p_ad, N, cf.H, cf.C);
        }
        // (li == 0: GEMM + attcoef already issued above)

        k_attn<<<N, 32 * cf.H>>>(p_as, p_ad, p_rowptr, p_srcs, p_w, p_invs, cf.H, Etot);
        int T = (F >= 128) ? (F >> 2) : 32;
        k_agg<<<N, T>>>(p_h, p_w, p_invs, p_rowptr, p_srcs, bi, p_agg, cf.H, cf.C, F, Etot);

        if (cf.bn) {
            const float* gamma = (const float*)d_in[cf.iW + 4];
            const float* beta  = (const float*)d_in[cf.iW + 5];
            k_zero_f2<<<1, F>>>(p_csum, p_csq, F);
            k_bnstats<<<240, F>>>(p_agg, p_csum, p_csq, N, F);
            k_bnapply_split<<<(N * F + 255) / 256, 256>>>(p_agg, p_y, p_ahi, p_alo,
                                                          p_csum, p_csq, gamma, beta, N, F);
            in = p_y;
        } else {
            k_logsoftmax16<<<(N + 255) / 256, 256>>>(p_agg, (float*)d_out, N);
        }
    }
}

// round 6
// speedup vs baseline: 1.9238x; 1.0184x over previous
#include <cuda_runtime.h>
#include <cuda_bf16.h>
#include <cstdint>
#include <math.h>

// ---------------------------------------------------------------------------
// GAT 4-layer network.
//   - CSR build (dst-sorted) once per call
//   - Layers 1-3: split-bf16 HMMA GEMM (mma.sync m16n8k16), 3-stage cp.async
//     pipeline, product-major MMA ordering (16-way accumulator independence),
//     attention coefficients fused into the epilogue.
//   - Layer 4: exact fp32 SIMT GEMM (tiny) + separate attcoef.
//   - per-node segment softmax (head-major edge buf), per-node aggregation
//     (float4 + unroll-8), BN+ELU (+bf16 re-split), log_softmax.
// ---------------------------------------------------------------------------

#define MAXN 20000
#define MAXE 360000
#define MAXF 512
#define MAXH 8
#define SCAN_B 512

__device__ float g_h[MAXN * MAXF];
__device__ float g_y[MAXN * MAXF];
__device__ float g_agg[MAXN * MAXF];
__device__ float g_as[MAXN * MAXH];
__device__ float g_ad[MAXN * MAXH];
__device__ float g_w[MAXE * MAXH];     // head-major: [H][Etot]
__device__ float g_invs[MAXN * MAXH];
__device__ int   g_deg[MAXN];
__device__ int   g_rowptr[MAXN + 1];
__device__ int   g_cursor[MAXN];
__device__ int   g_srcs[MAXE];
__device__ float g_colsum[MAXF];
__device__ float g_colsq[MAXF];
__device__ int   g_bsums[64];
__device__ __nv_bfloat16 g_ahi[MAXN * MAXF];
__device__ __nv_bfloat16 g_alo[MAXN * MAXF];
__device__ __nv_bfloat16 g_bhi[MAXF * MAXF];
__device__ __nv_bfloat16 g_blo[MAXF * MAXF];

// ---------------------------------------------------------------------------
// PTX helpers
// ---------------------------------------------------------------------------
__device__ __forceinline__ uint32_t smem_to_u32(const void* p) {
    uint32_t a;
    asm("{ .reg .u64 t; cvta.to.shared.u64 t, %1; cvt.u32.u64 %0, t; }" : "=r"(a) : "l"(p));
    return a;
}
__device__ __forceinline__ void cp16(uint32_t s, const void* g) {
    asm volatile("cp.async.cg.shared.global [%0], [%1], 16;" :: "r"(s), "l"(g));
}
__device__ __forceinline__ void ldsm_x4(uint32_t* r, uint32_t addr) {
    asm volatile("ldmatrix.sync.aligned.m8n8.x4.shared.b16 {%0,%1,%2,%3}, [%4];"
        : "=r"(r[0]), "=r"(r[1]), "=r"(r[2]), "=r"(r[3]) : "r"(addr));
}
__device__ __forceinline__ void ldsm_x4_t(uint32_t* r, uint32_t addr) {
    asm volatile("ldmatrix.sync.aligned.m8n8.x4.trans.shared.b16 {%0,%1,%2,%3}, [%4];"
        : "=r"(r[0]), "=r"(r[1]), "=r"(r[2]), "=r"(r[3]) : "r"(addr));
}
__device__ __forceinline__ void mma16816(float* c, const uint32_t* a, const uint32_t* b) {
    asm volatile("mma.sync.aligned.m16n8k16.row.col.f32.bf16.bf16.f32 "
        "{%0,%1,%2,%3}, {%4,%5,%6,%7}, {%8,%9}, {%0,%1,%2,%3};"
        : "+f"(c[0]), "+f"(c[1]), "+f"(c[2]), "+f"(c[3])
        : "r"(a[0]), "r"(a[1]), "r"(a[2]), "r"(a[3]), "r"(b[0]), "r"(b[1]));
}

// ---------------------------------------------------------------------------
// CSR build
// ---------------------------------------------------------------------------
__global__ void k_zero_int(int* p, int n) {
    int i = blockIdx.x * blockDim.x + threadIdx.x;
    if (i < n) p[i] = 0;
}

__global__ void k_hist(const int* __restrict__ ei, int E, int N, int* __restrict__ deg) {
    int e = blockIdx.x * blockDim.x + threadIdx.x;
    if (e >= E + N) return;
    int dst = (e < E) ? ei[E + e] : (e - E);
    atomicAdd(&deg[dst], 1);
}

__global__ void k_scan1(const int* __restrict__ deg, int* __restrict__ rowptr,
                        int* __restrict__ bsums, int n) {
    __shared__ int sh[SCAN_B];
    int i = blockIdx.x * SCAN_B + threadIdx.x;
    int v = (i < n) ? deg[i] : 0;
    sh[threadIdx.x] = v;
    __syncthreads();
    for (int off = 1; off < SCAN_B; off <<= 1) {
        int t = 0;
        if ((int)threadIdx.x >= off) t = sh[threadIdx.x - off];
        __syncthreads();
        sh[threadIdx.x] += t;
        __syncthreads();
    }
    if (i < n) rowptr[i] = sh[threadIdx.x] - v;
    if (threadIdx.x == SCAN_B - 1) bsums[blockIdx.x] = sh[SCAN_B - 1];
}

__global__ void k_scan2(int* bsums, int nb) {
    if (threadIdx.x == 0) {
        int run = 0;
        for (int i = 0; i < nb; i++) { int v = bsums[i]; bsums[i] = run; run += v; }
    }
}

__global__ void k_scan3(int* __restrict__ rowptr, const int* __restrict__ bsums,
                        int n, int etot, int* __restrict__ cursor) {
    int i = blockIdx.x * blockDim.x + threadIdx.x;
    if (i < n) {
        int v = rowptr[i] + bsums[i / SCAN_B];
        rowptr[i] = v;
        cursor[i] = v;
    }
    if (i == 0) rowptr[n] = etot;
}

__global__ void k_scatter(const int* __restrict__ ei, int E, int N,
                          int* __restrict__ cursor, int* __restrict__ srcs) {
    int e = blockIdx.x * blockDim.x + threadIdx.x;
    if (e >= E + N) return;
    int src, dst;
    if (e < E) { src = ei[e]; dst = ei[E + e]; }
    else       { src = dst = e - E; }
    int p = atomicAdd(&cursor[dst], 1);
    srcs[p] = src;
}

// ---------------------------------------------------------------------------
// fp32 -> (bf16 hi, bf16 lo) split
// ---------------------------------------------------------------------------
__global__ void k_split(const float* __restrict__ x, __nv_bfloat16* __restrict__ hi,
                        __nv_bfloat16* __restrict__ lo, int n) {
    int i = (blockIdx.x * blockDim.x + threadIdx.x) * 4;
    if (i >= n) return;
    float4 v = *(const float4*)(x + i);
    __nv_bfloat16 h0 = __float2bfloat16(v.x), h1 = __float2bfloat16(v.y);
    __nv_bfloat16 h2 = __float2bfloat16(v.z), h3 = __float2bfloat16(v.w);
    __nv_bfloat16 l0 = __float2bfloat16(v.x - __bfloat162float(h0));
    __nv_bfloat16 l1 = __float2bfloat16(v.y - __bfloat162float(h1));
    __nv_bfloat16 l2 = __float2bfloat16(v.z - __bfloat162float(h2));
    __nv_bfloat16 l3 = __float2bfloat16(v.w - __bfloat162float(h3));
    __nv_bfloat162* ph = (__nv_bfloat162*)(hi + i);
    __nv_bfloat162* pl = (__nv_bfloat162*)(lo + i);
    ph[0] = __nv_bfloat162(h0, h1); ph[1] = __nv_bfloat162(h2, h3);
    pl[0] = __nv_bfloat162(l0, l1); pl[1] = __nv_bfloat162(l2, l3);
}

// ---------------------------------------------------------------------------
// split-bf16 HMMA GEMM + fused attention coefficients.
// Product-major MMA ordering: 16 independent accumulators between reuses.
// ---------------------------------------------------------------------------
#define STAGE_BYTES 37888
#define OFF_ALO 10240
#define OFF_BHI 20480
#define OFF_BLO 29184
#define MMA_SMEM (3 * STAGE_BYTES)

__global__ void __launch_bounds__(256, 2) k_mma_gemm(
    const __nv_bfloat16* __restrict__ Ahi, const __nv_bfloat16* __restrict__ Alo,
    const __nv_bfloat16* __restrict__ Bhi, const __nv_bfloat16* __restrict__ Blo,
    float* __restrict__ C, int M, int K, int Nn,
    const float* __restrict__ att_s, const float* __restrict__ att_d,
    float* __restrict__ out_s, float* __restrict__ out_d, int H) {
    extern __shared__ char smem[];
    uint32_t sbu = smem_to_u32(smem);
    int tid = threadIdx.x, lane = tid & 31, wid = tid >> 5;
    int wm = wid & 1, wn = wid >> 1;
    int row0 = blockIdx.y * 128, col0 = blockIdx.x * 128;

    float c[4][4][4];
#pragma unroll
    for (int i = 0; i < 4; i++)
#pragma unroll
        for (int j = 0; j < 4; j++) {
            c[i][j][0] = 0.f; c[i][j][1] = 0.f; c[i][j][2] = 0.f; c[i][j][3] = 0.f;
        }

    int nch = K >> 5;

    auto issue = [&](int ch) {
        uint32_t sb = sbu + (uint32_t)(ch % 3) * STAGE_BYTES;
        int k0 = ch << 5;
#pragma unroll
        for (int i = 0; i < 2; i++) {
            int g = tid + i * 256;
            int r = g >> 2, c8 = (g & 3) << 3;
            int row = row0 + r;
            if (row >= M) row = M - 1;
            size_t ga = (size_t)row * K + k0 + c8;
            uint32_t sa = sb + r * 80 + (c8 << 1);
            cp16(sa, Ahi + ga);
            cp16(sa + OFF_ALO, Alo + ga);
            int rb = g >> 4, cb = (g & 15) << 3;
            size_t gb = (size_t)(k0 + rb) * Nn + col0 + cb;
            uint32_t sB = sb + OFF_BHI + rb * 272 + (cb << 1);
            cp16(sB, Bhi + gb);
            cp16(sB + (OFF_BLO - OFF_BHI), Blo + gb);
        }
        asm volatile("cp.async.commit_group;" ::: "memory");
    };

    issue(0);
    issue(1);
    for (int ch = 0; ch < nch; ch++) {
        if (ch + 1 < nch)
            asm volatile("cp.async.wait_group 1;" ::: "memory");
        else
            asm volatile("cp.async.wait_group 0;" ::: "memory");
        __syncthreads();
        if (ch + 2 < nch) issue(ch + 2);

        uint32_t sb = sbu + (uint32_t)(ch % 3) * STAGE_BYTES;
#pragma unroll
        for (int kk2 = 0; kk2 < 2; kk2++) {
            int kk = kk2 << 4;
            uint32_t ah[4][4], al[4][4], bh[2][4], bl[2][4];
#pragma unroll
            for (int mt = 0; mt < 4; mt++) {
                uint32_t aoff = sb + (uint32_t)(wm * 64 + mt * 16 + (lane & 15)) * 80
                              + ((kk + ((lane >> 4) << 3)) << 1);
                ldsm_x4(ah[mt], aoff);
                ldsm_x4(al[mt], aoff + OFF_ALO);
            }
#pragma unroll
            for (int nt2 = 0; nt2 < 2; nt2++) {
                uint32_t boff = sb + OFF_BHI + (uint32_t)(kk + (lane & 15)) * 272
                              + ((wn * 32 + nt2 * 16 + ((lane >> 4) << 3)) << 1);
                ldsm_x4_t(bh[nt2], boff);
                ldsm_x4_t(bl[nt2], boff + (OFF_BLO - OFF_BHI));
            }
            // product-major ordering: each accumulator touched once per 16 MMAs
#pragma unroll
            for (int mt = 0; mt < 4; mt++)
#pragma unroll
                for (int nt = 0; nt < 4; nt++)
                    mma16816(c[mt][nt], ah[mt], &bh[nt >> 1][(nt & 1) << 1]);
#pragma unroll
            for (int mt = 0; mt < 4; mt++)
#pragma unroll
                for (int nt = 0; nt < 4; nt++)
                    mma16816(c[mt][nt], ah[mt], &bl[nt >> 1][(nt & 1) << 1]);
#pragma unroll
            for (int mt = 0; mt < 4; mt++)
#pragma unroll
                for (int nt = 0; nt < 4; nt++)
                    mma16816(c[mt][nt], al[mt], &bh[nt >> 1][(nt & 1) << 1]);
        }
    }

    // ---- C store ----
#pragma unroll
    for (int mt = 0; mt < 4; mt++) {
        int r = row0 + wm * 64 + mt * 16 + (lane >> 2);
#pragma unroll
        for (int nt = 0; nt < 4; nt++) {
            int col = col0 + wn * 32 + nt * 8 + ((lane & 3) << 1);
            if (r < M) {
                float2 v = make_float2(c[mt][nt][0], c[mt][nt][1]);
                *(float2*)(C + (size_t)r * Nn + col) = v;
            }
            if (r + 8 < M) {
                float2 v = make_float2(c[mt][nt][2], c[mt][nt][3]);
                *(float2*)(C + (size_t)(r + 8) * Nn + col) = v;
            }
        }
    }

    // ---- fused attention coefficients ----
    __syncthreads();
    float* sred = (float*)smem;          // [2][128]
    float* dred = sred + 256;            // [2][128]
    sred[tid] = 0.f;
    dred[tid] = 0.f;
    __syncthreads();

    float asv[4][2], adv[4][2];
#pragma unroll
    for (int nt = 0; nt < 4; nt++) {
        int col = col0 + wn * 32 + nt * 8 + ((lane & 3) << 1);
        asv[nt][0] = att_s[col];     asv[nt][1] = att_s[col + 1];
        adv[nt][0] = att_d[col];     adv[nt][1] = att_d[col + 1];
    }
#pragma unroll
    for (int mt = 0; mt < 4; mt++) {
        float s0 = 0.f, s1 = 0.f, d0 = 0.f, d1 = 0.f;
#pragma unroll
        for (int nt = 0; nt < 4; nt++) {
            s0 += c[mt][nt][0] * asv[nt][0] + c[mt][nt][1] * asv[nt][1];
            s1 += c[mt][nt][2] * asv[nt][0] + c[mt][nt][3] * asv[nt][1];
            d0 += c[mt][nt][0] * adv[nt][0] + c[mt][nt][1] * adv[nt][1];
            d1 += c[mt][nt][2] * adv[nt][0] + c[mt][nt][3] * adv[nt][1];
        }
#pragma unroll
        for (int o = 1; o <= 2; o <<= 1) {
            s0 += __shfl_xor_sync(0xffffffffu, s0, o);
            s1 += __shfl_xor_sync(0xffffffffu, s1, o);
            d0 += __shfl_xor_sync(0xffffffffu, d0, o);
            d1 += __shfl_xor_sync(0xffffffffu, d1, o);
        }
        if ((lane & 3) == 0) {
            int hh = wn >> 1;
            int rloc = wm * 64 + mt * 16 + (lane >> 2);
            atomicAdd(&sred[hh * 128 + rloc], s0);
            atomicAdd(&sred[hh * 128 + rloc + 8], s1);
            atomicAdd(&dred[hh * 128 + rloc], d0);
            atomicAdd(&dred[hh * 128 + rloc + 8], d1);
        }
    }
    __syncthreads();
    {
        int hh = tid >> 7;
        int rloc = tid & 127;
        int row = row0 + rloc;
        if (row < M) {
            int hglob = (col0 >> 6) + hh;
            out_s[row * H + hglob] = sred[hh * 128 + rloc];
            out_d[row * H + hglob] = dred[hh * 128 + rloc];
        }
    }
}

// ---------------------------------------------------------------------------
// fp32 SIMT SGEMM (layer 4 only)
// ---------------------------------------------------------------------------
__global__ void k_sgemm(const float* __restrict__ A, const float* __restrict__ B,
                        float* __restrict__ C, int M, int K, int Nn) {
    __shared__ float As[16][68];
    __shared__ float Bs[16][68];
    int tid = threadIdx.x;
    int tx = tid & 15;
    int ty = tid >> 4;
    int row0 = blockIdx.y * 64;
    int col0 = blockIdx.x * 64;

    int arow = tid >> 2;
    int acol = (tid & 3) * 4;
    int brow = tid >> 4;
    int bcol = (tid & 15) * 4;

    float acc[4][4];
#pragma unroll
    for (int i = 0; i < 4; i++)
#pragma unroll
        for (int j = 0; j < 4; j++) acc[i][j] = 0.f;

    for (int k0 = 0; k0 < K; k0 += 16) {
        float4 av = make_float4(0.f, 0.f, 0.f, 0.f);
        if (row0 + arow < M)
            av = *(const float4*)(A + (size_t)(row0 + arow) * K + k0 + acol);
        As[acol + 0][arow] = av.x;
        As[acol + 1][arow] = av.y;
        As[acol + 2][arow] = av.z;
        As[acol + 3][arow] = av.w;

        float4 bv = make_float4(0.f, 0.f, 0.f, 0.f);
        if (col0 + bcol < Nn)
            bv = *(const float4*)(B + (size_t)(k0 + brow) * Nn + col0 + bcol);
        Bs[brow][bcol + 0] = bv.x;
        Bs[brow][bcol + 1] = bv.y;
        Bs[brow][bcol + 2] = bv.z;
        Bs[brow][bcol + 3] = bv.w;
        __syncthreads();

#pragma unroll
        for (int kk = 0; kk < 16; kk++) {
            float4 a4 = *(const float4*)&As[kk][ty * 4];
            float4 b4 = *(const float4*)&Bs[kk][tx * 4];
            float a[4] = {a4.x, a4.y, a4.z, a4.w};
            float b[4] = {b4.x, b4.y, b4.z, b4.w};
#pragma unroll
            for (int i = 0; i < 4; i++)
#pragma unroll
                for (int j = 0; j < 4; j++) acc[i][j] += a[i] * b[j];
        }
        __syncthreads();
    }

#pragma unroll
    for (int i = 0; i < 4; i++) {
        int r = row0 + ty * 4 + i;
        if (r >= M) break;
#pragma unroll
        for (int j = 0; j < 4; j++) {
            int cc = col0 + tx * 4 + j;
            if (cc < Nn) C[(size_t)r * Nn + cc] = acc[i][j];
        }
    }
}

// ---------------------------------------------------------------------------
// Attention coefficients (layer 4 only)
// ---------------------------------------------------------------------------
__global__ void k_attcoef(const float* __restrict__ h, const float* __restrict__ as,
                          const float* __restrict__ ad, float* __restrict__ out_s,
                          float* __restrict__ out_d, int N, int H, int C) {
    int wid = blockIdx.x * (blockDim.x >> 5) + (threadIdx.x >> 5);
    int lane = threadIdx.x & 31;
    if (wid >= N * H) return;
    int n = wid / H;
    int hh = wid - n * H;
    int F = H * C;
    const float* hr = h + (size_t)n * F + hh * C;
    const float* asr = as + hh * C;
    const float* adr = ad + hh * C;
    float s = 0.f, d = 0.f;
    for (int c = lane; c < C; c += 32) {
        float v = hr[c];
        s += v * asr[c];
        d += v * adr[c];
    }
#pragma unroll
    for (int o = 16; o; o >>= 1) {
        s += __shfl_xor_sync(0xffffffffu, s, o);
        d += __shfl_xor_sync(0xffffffffu, d, o);
    }
    if (lane == 0) {
        out_s[wid] = s;
        out_d[wid] = d;
    }
}

// ---------------------------------------------------------------------------
// Per-node segment softmax. w head-major [H][Etot].
// ---------------------------------------------------------------------------
__global__ void k_attn(const float* __restrict__ a_s, const float* __restrict__ a_d,
                       const int* __restrict__ rowptr, const int* __restrict__ srcs,
                       float* __restrict__ w, float* __restrict__ invs, int H, int Etot) {
    int n = blockIdx.x;
    int hh = threadIdx.x >> 5;
    int lane = threadIdx.x & 31;
    int st = rowptr[n], en = rowptr[n + 1];
    float adv = a_d[n * H + hh];
    float* wh = w + (size_t)hh * Etot;

    float mx = -1e30f;
    for (int i = st + lane; i < en; i += 32) {
        float v = a_s[srcs[i] * H + hh] + adv;
        v = v >= 0.f ? v : 0.2f * v;
        wh[i] = v;
        mx = fmaxf(mx, v);
    }
#pragma unroll
    for (int o = 16; o; o >>= 1) mx = fmaxf(mx, __shfl_xor_sync(0xffffffffu, mx, o));

    float sum = 0.f;
    for (int i = st + lane; i < en; i += 32) {
        float ex = __expf(wh[i] - mx);
        wh[i] = ex;
        sum += ex;
    }
#pragma unroll
    for (int o = 16; o; o >>= 1) sum += __shfl_xor_sync(0xffffffffu, sum, o);
    if (lane == 0) invs[n * H + hh] = 1.f / sum;
}

// ---------------------------------------------------------------------------
// Aggregation: block per node, float4 per thread, edge loop unrolled x8.
// ---------------------------------------------------------------------------
__global__ void k_agg(const float* __restrict__ h, const float* __restrict__ w,
                      const float* __restrict__ invs, const int* __restrict__ rowptr,
                      const int* __restrict__ srcs, const float* __restrict__ bias,
                      float* __restrict__ out, int H, int C, int F, int Etot) {
    int n = blockIdx.x;
    int f4 = threadIdx.x << 2;
    if (f4 >= F) return;
    int hh = f4 / C;
    const float* wh = w + (size_t)hh * Etot;
    int st = rowptr[n], en = rowptr[n + 1];
    float ci = invs[n * H + hh];
    float ax = 0.f, ay = 0.f, az = 0.f, aw = 0.f;

    int e = st;
    for (; e + 8 <= en; e += 8) {
        int s[8];
        float a[8];
#pragma unroll
        for (int j = 0; j < 8; j++) { s[j] = srcs[e + j]; a[j] = wh[e + j]; }
        float4 v[8];
#pragma unroll
        for (int j = 0; j < 8; j++) v[j] = *(const float4*)(h + (size_t)s[j] * F + f4);
#pragma unroll
        for (int j = 0; j < 8; j++) {
            ax += v[j].x * a[j];
            ay += v[j].y * a[j];
            az += v[j].z * a[j];
            aw += v[j].w * a[j];
        }
    }
    for (; e < en; e++) {
        int s = srcs[e];
        float a = wh[e];
        float4 v = *(const float4*)(h + (size_t)s * F + f4);
        ax += v.x * a; ay += v.y * a; az += v.z * a; aw += v.w * a;
    }
    float4 b = *(const float4*)(bias + f4);
    float4 o;
    o.x = ax * ci + b.x;
    o.y = ay * ci + b.y;
    o.z = az * ci + b.z;
    o.w = aw * ci + b.w;
    *(float4*)(out + (size_t)n * F + f4) = o;
}

// ---------------------------------------------------------------------------
// BatchNorm + ELU (fused with bf16 hi/lo split of the output)
// ---------------------------------------------------------------------------
__global__ void k_zero_f2(float* a, float* b, int n) {
    int i = blockIdx.x * blockDim.x + threadIdx.x;
    if (i < n) { a[i] = 0.f; b[i] = 0.f; }
}

__global__ void k_bnstats(const float* __restrict__ x, float* __restrict__ csum,
                          float* __restrict__ csq, int N, int F) {
    int c = threadIdx.x;
    float s = 0.f, sq = 0.f;
    for (int r = blockIdx.x; r < N; r += gridDim.x) {
        float v = x[(size_t)r * F + c];
        s += v;
        sq += v * v;
    }
    atomicAdd(&csum[c], s);
    atomicAdd(&csq[c], sq);
}

__global__ void k_bnapply_split(const float* __restrict__ in, float* __restrict__ out,
                                __nv_bfloat16* __restrict__ hi, __nv_bfloat16* __restrict__ lo,
                                const float* __restrict__ csum, const float* __restrict__ csq,
                                const float* __restrict__ gamma, const float* __restrict__ beta,
                                int N, int F) {
    int idx = blockIdx.x * blockDim.x + threadIdx.x;
    if (idx >= N * F) return;
    int c = idx % F;
    float invN = 1.f / (float)N;
    float mean = csum[c] * invN;
    float var = csq[c] * invN - mean * mean;
    float v = (in[idx] - mean) * rsqrtf(var + 1e-5f) * gamma[c] + beta[c];
    v = v > 0.f ? v : (__expf(v) - 1.f);
    out[idx] = v;
    __nv_bfloat16 h = __float2bfloat16(v);
    hi[idx] = h;
    lo[idx] = __float2bfloat16(v - __bfloat162float(h));
}

// ---------------------------------------------------------------------------
// log_softmax over 16 classes
// ---------------------------------------------------------------------------
__global__ void k_logsoftmax16(const float* __restrict__ in, float* __restrict__ out, int N) {
    int n = blockIdx.x * blockDim.x + threadIdx.x;
    if (n >= N) return;
    const float* r = in + n * 16;
    float mx = r[0];
#pragma unroll
    for (int j = 1; j < 16; j++) mx = fmaxf(mx, r[j]);
    float s = 0.f;
#pragma unroll
    for (int j = 0; j < 16; j++) s += __expf(r[j] - mx);
    float ls = logf(s) + mx;
    float* o = out + n * 16;
#pragma unroll
    for (int j = 0; j < 16; j++) o[j] = r[j] - ls;
}

// ---------------------------------------------------------------------------
// Host orchestration
// ---------------------------------------------------------------------------
extern "C" void kernel_launch(void* const* d_in, const int* in_sizes, int n_in,
                              void* d_out, int out_size) {
    const float* x = (const float*)d_in[0];
    const int* ei = (const int*)d_in[1];
    int N = in_sizes[0] / 512;
    int E = in_sizes[1] / 2;
    int Etot = E + N;

    float *p_h, *p_y, *p_agg, *p_as, *p_ad, *p_w, *p_invs, *p_csum, *p_csq;
    int *p_deg, *p_rowptr, *p_cursor, *p_srcs, *p_bsums;
    __nv_bfloat16 *p_ahi, *p_alo, *p_bhi, *p_blo;
    cudaGetSymbolAddress((void**)&p_h, g_h);
    cudaGetSymbolAddress((void**)&p_y, g_y);
    cudaGetSymbolAddress((void**)&p_agg, g_agg);
    cudaGetSymbolAddress((void**)&p_as, g_as);
    cudaGetSymbolAddress((void**)&p_ad, g_ad);
    cudaGetSymbolAddress((void**)&p_w, g_w);
    cudaGetSymbolAddress((void**)&p_invs, g_invs);
    cudaGetSymbolAddress((void**)&p_csum, g_colsum);
    cudaGetSymbolAddress((void**)&p_csq, g_colsq);
    cudaGetSymbolAddress((void**)&p_deg, g_deg);
    cudaGetSymbolAddress((void**)&p_rowptr, g_rowptr);
    cudaGetSymbolAddress((void**)&p_cursor, g_cursor);
    cudaGetSymbolAddress((void**)&p_srcs, g_srcs);
    cudaGetSymbolAddress((void**)&p_bsums, g_bsums);
    cudaGetSymbolAddress((void**)&p_ahi, g_ahi);
    cudaGetSymbolAddress((void**)&p_alo, g_alo);
    cudaGetSymbolAddress((void**)&p_bhi, g_bhi);
    cudaGetSymbolAddress((void**)&p_blo, g_blo);

    cudaFuncSetAttribute(k_mma_gemm, cudaFuncAttributeMaxDynamicSharedMemorySize, MMA_SMEM);

    struct Cfg { int Fin, H, C, iW; bool bn; };
    const Cfg cfgs[4] = {
        {512, 8, 64, 2, true},
        {512, 4, 64, 8, true},
        {256, 2, 64, 14, true},
        {128, 1, 16, 20, false},
    };

    // ---- Layer-1 prep + GEMM ----
    {
        int nel = N * 512;
        k_zero_int<<<(N + 255) / 256, 256>>>(p_deg, N);
        k_split<<<(nel / 4 + 255) / 256, 256>>>(x, p_ahi, p_alo, nel);
        int nw = 512 * 512;
        k_split<<<(nw / 4 + 255) / 256, 256>>>((const float*)d_in[2], p_bhi, p_blo, nw);
        dim3 gg(512 / 128, (N + 127) / 128);
        k_mma_gemm<<<gg, 256, MMA_SMEM>>>(p_ahi, p_alo, p_bhi, p_blo, p_h, N, 512, 512,
                                          (const float*)d_in[3], (const float*)d_in[4],
                                          p_as, p_ad, 8);
    }

    // ---- CSR build ----
    k_hist<<<(Etot + 255) / 256, 256>>>(ei, E, N, p_deg);
    int nblk = (N + SCAN_B - 1) / SCAN_B;
    k_scan1<<<nblk, SCAN_B>>>(p_deg, p_rowptr, p_bsums, N);
    k_scan2<<<1, 32>>>(p_bsums, nblk);
    k_scan3<<<(N + 255) / 256, 256>>>(p_rowptr, p_bsums, N, Etot, p_cursor);
    k_scatter<<<(Etot + 255) / 256, 256>>>(ei, E, N, p_cursor, p_srcs);

    const float* in = x;
    for (int li = 0; li < 4; li++) {
        const Cfg& cf = cfgs[li];
        int F = cf.H * cf.C;
        const float* W  = (const float*)d_in[cf.iW + 0];
        const float* as = (const float*)d_in[cf.iW + 1];
        const float* ad = (const float*)d_in[cf.iW + 2];
        const float* bi = (const float*)d_in[cf.iW + 3];

        if (li >= 1 && li < 3) {
            int nw = cf.Fin * F;
            k_split<<<(nw / 4 + 255) / 256, 256>>>(W, p_bhi, p_blo, nw);
            dim3 gg(F / 128, (N + 127) / 128);
            k_mma_gemm<<<gg, 256, MMA_SMEM>>>(p_ahi, p_alo, p_bhi, p_blo, p_h, N, cf.Fin, F,
                                              as, ad, p_as, p_ad, cf.H);
        } else if (li == 3) {
            dim3 ggrid((F + 63) / 64, (N + 63) / 64);
            k_sgemm<<<ggrid, 256>>>(in, W, p_h, N, cf.Fin, F);
            int pairs = N * cf.H;
            k_attcoef<<<(pairs + 3) / 4, 128>>>(p_h, as, ad, p_as, p_ad, N, cf.H, cf.C);
        }

        k_attn<<<N, 32 * cf.H>>>(p_as, p_ad, p_rowptr, p_srcs, p_w, p_invs, cf.H, Etot);
        int T = (F >= 128) ? (F >> 2) : 32;
        k_agg<<<N, T>>>(p_h, p_w, p_invs, p_rowptr, p_srcs, bi, p_agg, cf.H, cf.C, F, Etot);

        if (cf.bn) {
            const float* gamma = (const float*)d_in[cf.iW + 4];
            const float* beta  = (const float*)d_in[cf.iW + 5];
            k_zero_f2<<<1, F>>>(p_csum, p_csq, F);
            k_bnstats<<<240, F>>>(p_agg, p_csum, p_csq, N, F);
            k_bnapply_split<<<(N * F + 255) / 256, 256>>>(p_agg, p_y, p_ahi, p_alo,
                                                          p_csum, p_csq, gamma, beta, N, F);
            in = p_y;
        } else {
            k_logsoftmax16<<<(N + 255) / 256, 256>>>(p_agg, (float*)d_out, N);
        }
    }
}